// round 1
// baseline (speedup 1.0000x reference)
#include <cuda_runtime.h>
#include <cuda_bf16.h>
#include <math.h>

#define BATCH 8
#define CH    64
#define NPIX  4096   // 64*64

// Scratch in device globals (no allocations allowed).
__device__ float g_f[BATCH * CH * NPIX];
__device__ float g_g[BATCH * CH * NPIX];
__device__ float g_h[BATCH * CH * NPIX];
__device__ float g_m[BATCH * NPIX];
__device__ float g_z[BATCH * NPIX];

// ---------------------------------------------------------------------------
// Stage A: f/g/h = W @ x + b  (per-pixel 1x1 conv, 3 small GEMMs)
// grid (NPIX/256, BATCH), 256 threads; each thread owns one pixel column.
// ---------------------------------------------------------------------------
__global__ __launch_bounds__(256) void fgh_kernel(
    const float* __restrict__ x,
    const float* __restrict__ Wf, const float* __restrict__ bf,
    const float* __restrict__ Wg, const float* __restrict__ bg,
    const float* __restrict__ Wh, const float* __restrict__ bh)
{
    __shared__ float sW[CH * CH];
    __shared__ float sb[CH];

    const int b = blockIdx.y;
    const int n = blockIdx.x * 256 + threadIdx.x;

    // Load this pixel's channel vector into registers (coalesced across threads).
    float xc[CH];
    const float* xb = x + (size_t)b * CH * NPIX + n;
#pragma unroll
    for (int c = 0; c < CH; c++) xc[c] = xb[(size_t)c * NPIX];

    const float* Ws[3] = {Wf, Wg, Wh};
    const float* bs[3] = {bf, bg, bh};
    float* outs[3];
    outs[0] = g_f; outs[1] = g_g; outs[2] = g_h;

    for (int mtx = 0; mtx < 3; mtx++) {
        __syncthreads();
        for (int q = threadIdx.x; q < CH * CH; q += 256) sW[q] = Ws[mtx][q];
        if (threadIdx.x < CH) sb[threadIdx.x] = bs[mtx][threadIdx.x];
        __syncthreads();

        float* dst = outs[mtx] + (size_t)b * CH * NPIX + n;
        for (int o = 0; o < CH; o++) {
            float acc = sb[o];
            const float4* w4 = (const float4*)(sW + o * CH);
#pragma unroll
            for (int c4 = 0; c4 < CH / 4; c4++) {
                float4 w = w4[c4];
                acc += w.x * xc[c4 * 4 + 0];
                acc += w.y * xc[c4 * 4 + 1];
                acc += w.z * xc[c4 * 4 + 2];
                acc += w.w * xc[c4 * 4 + 3];
            }
            dst[(size_t)o * NPIX] = acc;
        }
    }
}

// ---------------------------------------------------------------------------
// Pass 1: per-row (over i) online softmax stats m[i], Z[i] of s[i,j]=f[:,i].g[:,j]
// grid (NPIX/128, BATCH), 256 threads. 128x128x64 tile, 8x8 micro-tile/thread.
// Dynamic smem: fs[64][128] + gs[64][128] = 64 KB.
// ---------------------------------------------------------------------------
__global__ __launch_bounds__(256, 1) void pass1_kernel()
{
    extern __shared__ float sm[];
    float* fs = sm;            // 8192 floats
    float* gs = sm + 8192;     // 8192 floats

    const int b  = blockIdx.y;
    const int i0 = blockIdx.x * 128;
    const int t  = threadIdx.x;
    const int tx = t & 15;
    const int ty = t >> 4;

    const float* fb = g_f + (size_t)b * CH * NPIX;
    const float* gb = g_g + (size_t)b * CH * NPIX;

    // Load the fixed f (i) tile: fs[c][i], i contiguous.
    {
        float4* fs4 = (float4*)fs;
        for (int q = t; q < 2048; q += 256) {
            int c = q >> 5, i4 = (q & 31) * 4;
            fs4[q] = *(const float4*)(fb + (size_t)c * NPIX + i0 + i4);
        }
    }

    float m[8], z[8];
#pragma unroll
    for (int r = 0; r < 8; r++) { m[r] = -1e30f; z[r] = 0.0f; }

    for (int jt = 0; jt < NPIX / 128; jt++) {
        __syncthreads();
        {
            float4* gs4 = (float4*)gs;
            const int j0 = jt * 128;
            for (int q = t; q < 2048; q += 256) {
                int c = q >> 5, i4 = (q & 31) * 4;
                gs4[q] = *(const float4*)(gb + (size_t)c * NPIX + j0 + i4);
            }
        }
        __syncthreads();

        float acc[8][8];
#pragma unroll
        for (int r = 0; r < 8; r++)
#pragma unroll
            for (int cc = 0; cc < 8; cc++) acc[r][cc] = 0.0f;

        const float4* fsc = (const float4*)fs;
        const float4* gsc = (const float4*)gs;
#pragma unroll 4
        for (int c = 0; c < CH; c++) {
            float4 a0 = fsc[c * 32 + ty];
            float4 a1 = fsc[c * 32 + 16 + ty];
            float4 b0 = gsc[c * 32 + tx];
            float4 b1 = gsc[c * 32 + 16 + tx];
            float av[8] = {a0.x, a0.y, a0.z, a0.w, a1.x, a1.y, a1.z, a1.w};
            float bv[8] = {b0.x, b0.y, b0.z, b0.w, b1.x, b1.y, b1.z, b1.w};
#pragma unroll
            for (int r = 0; r < 8; r++)
#pragma unroll
                for (int cc = 0; cc < 8; cc++)
                    acc[r][cc] += av[r] * bv[cc];
        }

        // Online softmax update over this tile's 8 local columns per row.
#pragma unroll
        for (int r = 0; r < 8; r++) {
            float tm = acc[r][0];
#pragma unroll
            for (int cc = 1; cc < 8; cc++) tm = fmaxf(tm, acc[r][cc]);
            float mn = fmaxf(m[r], tm);
            float s = 0.0f;
#pragma unroll
            for (int cc = 0; cc < 8; cc++) s += __expf(acc[r][cc] - mn);
            z[r] = z[r] * __expf(m[r] - mn) + s;
            m[r] = mn;
        }
    }

    // Cross-thread (over tx) merge of (m, z) per row; reuse fs region.
    __syncthreads();
    float2* red = (float2*)sm;   // [128][16]
#pragma unroll
    for (int r = 0; r < 8; r++) {
        int row = (r < 4) ? (ty * 4 + r) : (64 + ty * 4 + (r - 4));
        red[row * 16 + tx] = make_float2(m[r], z[r]);
    }
    __syncthreads();
    if (t < 128) {
        float M = -1e30f;
#pragma unroll
        for (int k = 0; k < 16; k++) M = fmaxf(M, red[t * 16 + k].x);
        float Z = 0.0f;
#pragma unroll
        for (int k = 0; k < 16; k++) {
            float2 v = red[t * 16 + k];
            Z += v.y * __expf(v.x - M);
        }
        g_m[b * NPIX + i0 + t] = M;
        g_z[b * NPIX + i0 + t] = Z;
    }
}

// ---------------------------------------------------------------------------
// Pass 2: out[c, j] = sum_i (h[c,i]/Z[i]) * exp(s[i,j]-m[i]); final = gamma*out + x
// grid (NPIX/128, BATCH), 256 threads.
// Dynamic smem: gs(32K) + fs(32K) + hs(32K) + ps(64K) + ms/rz(1K) = 161.5 KB.
// ---------------------------------------------------------------------------
__global__ __launch_bounds__(256, 1) void pass2_kernel(
    const float* __restrict__ x,
    const float* __restrict__ gamma,
    float* __restrict__ out)
{
    extern __shared__ float sm[];
    float* gs = sm;              // 8192
    float* fs = sm + 8192;       // 8192
    float* hs = sm + 16384;      // 8192  (h / Z, [c][i])
    float* ps = sm + 24576;      // 16384 (p = exp(s - m), [i][j])
    float* ms = sm + 40960;      // 128
    float* rz = sm + 41088;      // 128

    const int b  = blockIdx.y;
    const int j0 = blockIdx.x * 128;
    const int t  = threadIdx.x;
    const int tx = t & 15;
    const int ty = t >> 4;

    const float* gb = g_g + (size_t)b * CH * NPIX;
    const float* fb = g_f + (size_t)b * CH * NPIX;
    const float* hb = g_h + (size_t)b * CH * NPIX;

    // Fixed g (j) tile.
    {
        float4* gs4 = (float4*)gs;
        for (int q = t; q < 2048; q += 256) {
            int c = q >> 5, i4 = (q & 31) * 4;
            gs4[q] = *(const float4*)(gb + (size_t)c * NPIX + j0 + i4);
        }
    }

    float o[4][8];
#pragma unroll
    for (int r = 0; r < 4; r++)
#pragma unroll
        for (int cc = 0; cc < 8; cc++) o[r][cc] = 0.0f;

    for (int it = 0; it < NPIX / 128; it++) {
        const int i0 = it * 128;
        __syncthreads();   // previous iter consumers done with fs/hs/ps/ms/rz
        if (t < 128) {
            ms[t] = g_m[b * NPIX + i0 + t];
            rz[t] = 1.0f / g_z[b * NPIX + i0 + t];
        }
        __syncthreads();

        {
            float4* fs4 = (float4*)fs;
            float4* hs4 = (float4*)hs;
            const float4* rz4 = (const float4*)rz;
            for (int q = t; q < 2048; q += 256) {
                int c = q >> 5, i4 = (q & 31) * 4;
                fs4[q] = *(const float4*)(fb + (size_t)c * NPIX + i0 + i4);
                float4 hv = *(const float4*)(hb + (size_t)c * NPIX + i0 + i4);
                float4 rv = rz4[q & 31];
                hv.x *= rv.x; hv.y *= rv.y; hv.z *= rv.z; hv.w *= rv.w;
                hs4[q] = hv;
            }
        }
        __syncthreads();

        // s tile: rows = i (from fs), cols = j (from gs)
        float acc[8][8];
#pragma unroll
        for (int r = 0; r < 8; r++)
#pragma unroll
            for (int cc = 0; cc < 8; cc++) acc[r][cc] = 0.0f;

        const float4* fsc = (const float4*)fs;
        const float4* gsc = (const float4*)gs;
#pragma unroll 4
        for (int c = 0; c < CH; c++) {
            float4 a0 = fsc[c * 32 + ty];
            float4 a1 = fsc[c * 32 + 16 + ty];
            float4 b0 = gsc[c * 32 + tx];
            float4 b1 = gsc[c * 32 + 16 + tx];
            float av[8] = {a0.x, a0.y, a0.z, a0.w, a1.x, a1.y, a1.z, a1.w};
            float bv[8] = {b0.x, b0.y, b0.z, b0.w, b1.x, b1.y, b1.z, b1.w};
#pragma unroll
            for (int r = 0; r < 8; r++)
#pragma unroll
                for (int cc = 0; cc < 8; cc++)
                    acc[r][cc] += av[r] * bv[cc];
        }

        // p = exp(s - m[i]) -> ps[i][j]
        {
            float4* ps4 = (float4*)ps;
#pragma unroll
            for (int r = 0; r < 8; r++) {
                int row = (r < 4) ? (ty * 4 + r) : (64 + ty * 4 + (r - 4));
                float mr = ms[row];
                float4 p0, p1;
                p0.x = __expf(acc[r][0] - mr);
                p0.y = __expf(acc[r][1] - mr);
                p0.z = __expf(acc[r][2] - mr);
                p0.w = __expf(acc[r][3] - mr);
                p1.x = __expf(acc[r][4] - mr);
                p1.y = __expf(acc[r][5] - mr);
                p1.z = __expf(acc[r][6] - mr);
                p1.w = __expf(acc[r][7] - mr);
                ps4[row * 32 + tx]      = p0;
                ps4[row * 32 + 16 + tx] = p1;
            }
        }
        __syncthreads();

        // out accumulate: o[c][j] += sum_ii hs[c][ii] * ps[ii][j]
        const float4* hsc = (const float4*)hs;
        const float4* psc = (const float4*)ps;
#pragma unroll 2
        for (int ii4 = 0; ii4 < 32; ii4++) {
            float a_arr[4][4];
#pragma unroll
            for (int r = 0; r < 4; r++) {
                float4 a = hsc[(ty * 4 + r) * 32 + ii4];
                a_arr[r][0] = a.x; a_arr[r][1] = a.y;
                a_arr[r][2] = a.z; a_arr[r][3] = a.w;
            }
#pragma unroll
            for (int u = 0; u < 4; u++) {
                int ii = ii4 * 4 + u;
                float4 p0 = psc[ii * 32 + tx];
                float4 p1 = psc[ii * 32 + 16 + tx];
                float pv[8] = {p0.x, p0.y, p0.z, p0.w, p1.x, p1.y, p1.z, p1.w};
#pragma unroll
                for (int r = 0; r < 4; r++)
#pragma unroll
                    for (int cc = 0; cc < 8; cc++)
                        o[r][cc] += a_arr[r][u] * pv[cc];
            }
        }
    }

    // Epilogue: final = gamma*out + x
    const float gam = *gamma;
#pragma unroll
    for (int r = 0; r < 4; r++) {
        int c = ty * 4 + r;
        const float* xp = x   + ((size_t)b * CH + c) * NPIX + j0;
        float*       op = out + ((size_t)b * CH + c) * NPIX + j0;

        float4 x0 = *(const float4*)(xp + tx * 4);
        float4 x1 = *(const float4*)(xp + 64 + tx * 4);
        float4 r0, r1;
        r0.x = gam * o[r][0] + x0.x;
        r0.y = gam * o[r][1] + x0.y;
        r0.z = gam * o[r][2] + x0.z;
        r0.w = gam * o[r][3] + x0.w;
        r1.x = gam * o[r][4] + x1.x;
        r1.y = gam * o[r][5] + x1.y;
        r1.z = gam * o[r][6] + x1.z;
        r1.w = gam * o[r][7] + x1.w;
        *(float4*)(op + tx * 4)      = r0;
        *(float4*)(op + 64 + tx * 4) = r1;
    }
}

// ---------------------------------------------------------------------------
extern "C" void kernel_launch(void* const* d_in, const int* in_sizes, int n_in,
                              void* d_out, int out_size)
{
    const float* x     = (const float*)d_in[0];
    const float* Wf    = (const float*)d_in[1];
    const float* bf    = (const float*)d_in[2];
    const float* Wg    = (const float*)d_in[3];
    const float* bg    = (const float*)d_in[4];
    const float* Wh    = (const float*)d_in[5];
    const float* bh    = (const float*)d_in[6];
    const float* gamma = (const float*)d_in[7];
    float* out = (float*)d_out;

    (void)in_sizes; (void)n_in; (void)out_size;

    cudaFuncSetAttribute(pass1_kernel, cudaFuncAttributeMaxDynamicSharedMemorySize,
                         16384 * sizeof(float));
    cudaFuncSetAttribute(pass2_kernel, cudaFuncAttributeMaxDynamicSharedMemorySize,
                         41216 * sizeof(float));

    fgh_kernel<<<dim3(NPIX / 256, BATCH), 256>>>(x, Wf, bf, Wg, bg, Wh, bh);
    pass1_kernel<<<dim3(NPIX / 128, BATCH), 256, 16384 * sizeof(float)>>>();
    pass2_kernel<<<dim3(NPIX / 128, BATCH), 256, 41216 * sizeof(float)>>>(x, gamma, out);
}

// round 2
// speedup vs baseline: 1.0009x; 1.0009x over previous
#include <cuda_runtime.h>
#include <cuda_bf16.h>
#include <math.h>

#define BATCH 8
#define CH    64
#define NPIX  4096   // 64*64

// Scratch in device globals (no allocations allowed).
__device__ float g_f[BATCH * CH * NPIX];
__device__ float g_g[BATCH * CH * NPIX];
__device__ float g_h[BATCH * CH * NPIX];
__device__ float g_m[BATCH * NPIX];
__device__ float g_z[BATCH * NPIX];

// ---------------------------------------------------------------------------
// Stage A: f/g/h = W @ x + b  (per-pixel 1x1 conv, 3 small GEMMs)
// grid (NPIX/256, BATCH), 256 threads; each thread owns one pixel column.
// ---------------------------------------------------------------------------
__global__ __launch_bounds__(256) void fgh_kernel(
    const float* __restrict__ x,
    const float* __restrict__ Wf, const float* __restrict__ bf,
    const float* __restrict__ Wg, const float* __restrict__ bg,
    const float* __restrict__ Wh, const float* __restrict__ bh)
{
    __shared__ float sW[CH * CH];
    __shared__ float sb[CH];

    const int b = blockIdx.y;
    const int n = blockIdx.x * 256 + threadIdx.x;

    // Load this pixel's channel vector into registers (coalesced across threads).
    float xc[CH];
    const float* xb = x + (size_t)b * CH * NPIX + n;
#pragma unroll
    for (int c = 0; c < CH; c++) xc[c] = xb[(size_t)c * NPIX];

    const float* Ws[3] = {Wf, Wg, Wh};
    const float* bs[3] = {bf, bg, bh};
    float* outs[3];
    outs[0] = g_f; outs[1] = g_g; outs[2] = g_h;

    for (int mtx = 0; mtx < 3; mtx++) {
        __syncthreads();
        for (int q = threadIdx.x; q < CH * CH; q += 256) sW[q] = Ws[mtx][q];
        if (threadIdx.x < CH) sb[threadIdx.x] = bs[mtx][threadIdx.x];
        __syncthreads();

        float* dst = outs[mtx] + (size_t)b * CH * NPIX + n;
        for (int o = 0; o < CH; o++) {
            float acc = sb[o];
            const float4* w4 = (const float4*)(sW + o * CH);
#pragma unroll
            for (int c4 = 0; c4 < CH / 4; c4++) {
                float4 w = w4[c4];
                acc += w.x * xc[c4 * 4 + 0];
                acc += w.y * xc[c4 * 4 + 1];
                acc += w.z * xc[c4 * 4 + 2];
                acc += w.w * xc[c4 * 4 + 3];
            }
            dst[(size_t)o * NPIX] = acc;
        }
    }
}

// ---------------------------------------------------------------------------
// Pass 1: per-row (over i) online softmax stats m[i], Z[i] of s[i,j]=f[:,i].g[:,j]
// grid (NPIX/128, BATCH), 256 threads. 128x128x64 tile, 8x8 micro-tile/thread.
// Dynamic smem: fs[64][128] + gs[64][128] = 64 KB.
// ---------------------------------------------------------------------------
__global__ __launch_bounds__(256, 1) void pass1_kernel()
{
    extern __shared__ float sm[];
    float* fs = sm;            // 8192 floats
    float* gs = sm + 8192;     // 8192 floats

    const int b  = blockIdx.y;
    const int i0 = blockIdx.x * 128;
    const int t  = threadIdx.x;
    const int tx = t & 15;
    const int ty = t >> 4;

    const float* fb = g_f + (size_t)b * CH * NPIX;
    const float* gb = g_g + (size_t)b * CH * NPIX;

    // Load the fixed f (i) tile: fs[c][i], i contiguous.
    {
        float4* fs4 = (float4*)fs;
        for (int q = t; q < 2048; q += 256) {
            int c = q >> 5, i4 = (q & 31) * 4;
            fs4[q] = *(const float4*)(fb + (size_t)c * NPIX + i0 + i4);
        }
    }

    float m[8], z[8];
#pragma unroll
    for (int r = 0; r < 8; r++) { m[r] = -1e30f; z[r] = 0.0f; }

    for (int jt = 0; jt < NPIX / 128; jt++) {
        __syncthreads();
        {
            float4* gs4 = (float4*)gs;
            const int j0 = jt * 128;
            for (int q = t; q < 2048; q += 256) {
                int c = q >> 5, i4 = (q & 31) * 4;
                gs4[q] = *(const float4*)(gb + (size_t)c * NPIX + j0 + i4);
            }
        }
        __syncthreads();

        float acc[8][8];
#pragma unroll
        for (int r = 0; r < 8; r++)
#pragma unroll
            for (int cc = 0; cc < 8; cc++) acc[r][cc] = 0.0f;

        const float4* fsc = (const float4*)fs;
        const float4* gsc = (const float4*)gs;
#pragma unroll 4
        for (int c = 0; c < CH; c++) {
            float4 a0 = fsc[c * 32 + ty];
            float4 a1 = fsc[c * 32 + 16 + ty];
            float4 b0 = gsc[c * 32 + tx];
            float4 b1 = gsc[c * 32 + 16 + tx];
            float av[8] = {a0.x, a0.y, a0.z, a0.w, a1.x, a1.y, a1.z, a1.w};
            float bv[8] = {b0.x, b0.y, b0.z, b0.w, b1.x, b1.y, b1.z, b1.w};
#pragma unroll
            for (int r = 0; r < 8; r++)
#pragma unroll
                for (int cc = 0; cc < 8; cc++)
                    acc[r][cc] += av[r] * bv[cc];
        }

        // Online softmax update over this tile's 8 local columns per row.
#pragma unroll
        for (int r = 0; r < 8; r++) {
            float tm = acc[r][0];
#pragma unroll
            for (int cc = 1; cc < 8; cc++) tm = fmaxf(tm, acc[r][cc]);
            float mn = fmaxf(m[r], tm);
            float s = 0.0f;
#pragma unroll
            for (int cc = 0; cc < 8; cc++) s += __expf(acc[r][cc] - mn);
            z[r] = z[r] * __expf(m[r] - mn) + s;
            m[r] = mn;
        }
    }

    // Cross-thread (over tx) merge of (m, z) per row; reuse fs region.
    __syncthreads();
    float2* red = (float2*)sm;   // [128][16]
#pragma unroll
    for (int r = 0; r < 8; r++) {
        int row = (r < 4) ? (ty * 4 + r) : (64 + ty * 4 + (r - 4));
        red[row * 16 + tx] = make_float2(m[r], z[r]);
    }
    __syncthreads();
    if (t < 128) {
        float M = -1e30f;
#pragma unroll
        for (int k = 0; k < 16; k++) M = fmaxf(M, red[t * 16 + k].x);
        float Z = 0.0f;
#pragma unroll
        for (int k = 0; k < 16; k++) {
            float2 v = red[t * 16 + k];
            Z += v.y * __expf(v.x - M);
        }
        g_m[b * NPIX + i0 + t] = M;
        g_z[b * NPIX + i0 + t] = Z;
    }
}

// ---------------------------------------------------------------------------
// Pass 2: out[c, j] = sum_i (h[c,i]/Z[i]) * exp(s[i,j]-m[i]); final = gamma*out + x
// grid (NPIX/128, BATCH), 256 threads.
// Dynamic smem: gs(32K) + fs(32K) + hs(32K) + ps(64K) + ms/rz(1K) = 161.5 KB.
// ---------------------------------------------------------------------------
__global__ __launch_bounds__(256, 1) void pass2_kernel(
    const float* __restrict__ x,
    const float* __restrict__ gamma,
    float* __restrict__ out)
{
    extern __shared__ float sm[];
    float* gs = sm;              // 8192
    float* fs = sm + 8192;       // 8192
    float* hs = sm + 16384;      // 8192  (h / Z, [c][i])
    float* ps = sm + 24576;      // 16384 (p = exp(s - m), [i][j])
    float* ms = sm + 40960;      // 128
    float* rz = sm + 41088;      // 128

    const int b  = blockIdx.y;
    const int j0 = blockIdx.x * 128;
    const int t  = threadIdx.x;
    const int tx = t & 15;
    const int ty = t >> 4;

    const float* gb = g_g + (size_t)b * CH * NPIX;
    const float* fb = g_f + (size_t)b * CH * NPIX;
    const float* hb = g_h + (size_t)b * CH * NPIX;

    // Fixed g (j) tile.
    {
        float4* gs4 = (float4*)gs;
        for (int q = t; q < 2048; q += 256) {
            int c = q >> 5, i4 = (q & 31) * 4;
            gs4[q] = *(const float4*)(gb + (size_t)c * NPIX + j0 + i4);
        }
    }

    float o[4][8];
#pragma unroll
    for (int r = 0; r < 4; r++)
#pragma unroll
        for (int cc = 0; cc < 8; cc++) o[r][cc] = 0.0f;

    for (int it = 0; it < NPIX / 128; it++) {
        const int i0 = it * 128;
        __syncthreads();   // previous iter consumers done with fs/hs/ps/ms/rz
        if (t < 128) {
            ms[t] = g_m[b * NPIX + i0 + t];
            rz[t] = 1.0f / g_z[b * NPIX + i0 + t];
        }
        __syncthreads();

        {
            float4* fs4 = (float4*)fs;
            float4* hs4 = (float4*)hs;
            const float4* rz4 = (const float4*)rz;
            for (int q = t; q < 2048; q += 256) {
                int c = q >> 5, i4 = (q & 31) * 4;
                fs4[q] = *(const float4*)(fb + (size_t)c * NPIX + i0 + i4);
                float4 hv = *(const float4*)(hb + (size_t)c * NPIX + i0 + i4);
                float4 rv = rz4[q & 31];
                hv.x *= rv.x; hv.y *= rv.y; hv.z *= rv.z; hv.w *= rv.w;
                hs4[q] = hv;
            }
        }
        __syncthreads();

        // s tile: rows = i (from fs), cols = j (from gs)
        float acc[8][8];
#pragma unroll
        for (int r = 0; r < 8; r++)
#pragma unroll
            for (int cc = 0; cc < 8; cc++) acc[r][cc] = 0.0f;

        const float4* fsc = (const float4*)fs;
        const float4* gsc = (const float4*)gs;
#pragma unroll 4
        for (int c = 0; c < CH; c++) {
            float4 a0 = fsc[c * 32 + ty];
            float4 a1 = fsc[c * 32 + 16 + ty];
            float4 b0 = gsc[c * 32 + tx];
            float4 b1 = gsc[c * 32 + 16 + tx];
            float av[8] = {a0.x, a0.y, a0.z, a0.w, a1.x, a1.y, a1.z, a1.w};
            float bv[8] = {b0.x, b0.y, b0.z, b0.w, b1.x, b1.y, b1.z, b1.w};
#pragma unroll
            for (int r = 0; r < 8; r++)
#pragma unroll
                for (int cc = 0; cc < 8; cc++)
                    acc[r][cc] += av[r] * bv[cc];
        }

        // p = exp(s - m[i]) -> ps[i][j]
        {
            float4* ps4 = (float4*)ps;
#pragma unroll
            for (int r = 0; r < 8; r++) {
                int row = (r < 4) ? (ty * 4 + r) : (64 + ty * 4 + (r - 4));
                float mr = ms[row];
                float4 p0, p1;
                p0.x = __expf(acc[r][0] - mr);
                p0.y = __expf(acc[r][1] - mr);
                p0.z = __expf(acc[r][2] - mr);
                p0.w = __expf(acc[r][3] - mr);
                p1.x = __expf(acc[r][4] - mr);
                p1.y = __expf(acc[r][5] - mr);
                p1.z = __expf(acc[r][6] - mr);
                p1.w = __expf(acc[r][7] - mr);
                ps4[row * 32 + tx]      = p0;
                ps4[row * 32 + 16 + tx] = p1;
            }
        }
        __syncthreads();

        // out accumulate: o[c][j] += sum_ii hs[c][ii] * ps[ii][j]
        const float4* hsc = (const float4*)hs;
        const float4* psc = (const float4*)ps;
#pragma unroll 2
        for (int ii4 = 0; ii4 < 32; ii4++) {
            float a_arr[4][4];
#pragma unroll
            for (int r = 0; r < 4; r++) {
                float4 a = hsc[(ty * 4 + r) * 32 + ii4];
                a_arr[r][0] = a.x; a_arr[r][1] = a.y;
                a_arr[r][2] = a.z; a_arr[r][3] = a.w;
            }
#pragma unroll
            for (int u = 0; u < 4; u++) {
                int ii = ii4 * 4 + u;
                float4 p0 = psc[ii * 32 + tx];
                float4 p1 = psc[ii * 32 + 16 + tx];
                float pv[8] = {p0.x, p0.y, p0.z, p0.w, p1.x, p1.y, p1.z, p1.w};
#pragma unroll
                for (int r = 0; r < 4; r++)
#pragma unroll
                    for (int cc = 0; cc < 8; cc++)
                        o[r][cc] += a_arr[r][u] * pv[cc];
            }
        }
    }

    // Epilogue: final = gamma*out + x
    const float gam = *gamma;
#pragma unroll
    for (int r = 0; r < 4; r++) {
        int c = ty * 4 + r;
        const float* xp = x   + ((size_t)b * CH + c) * NPIX + j0;
        float*       op = out + ((size_t)b * CH + c) * NPIX + j0;

        float4 x0 = *(const float4*)(xp + tx * 4);
        float4 x1 = *(const float4*)(xp + 64 + tx * 4);
        float4 r0, r1;
        r0.x = gam * o[r][0] + x0.x;
        r0.y = gam * o[r][1] + x0.y;
        r0.z = gam * o[r][2] + x0.z;
        r0.w = gam * o[r][3] + x0.w;
        r1.x = gam * o[r][4] + x1.x;
        r1.y = gam * o[r][5] + x1.y;
        r1.z = gam * o[r][6] + x1.z;
        r1.w = gam * o[r][7] + x1.w;
        *(float4*)(op + tx * 4)      = r0;
        *(float4*)(op + 64 + tx * 4) = r1;
    }
}

// ---------------------------------------------------------------------------
extern "C" void kernel_launch(void* const* d_in, const int* in_sizes, int n_in,
                              void* d_out, int out_size)
{
    const float* x     = (const float*)d_in[0];
    const float* Wf    = (const float*)d_in[1];
    const float* bf    = (const float*)d_in[2];
    const float* Wg    = (const float*)d_in[3];
    const float* bg    = (const float*)d_in[4];
    const float* Wh    = (const float*)d_in[5];
    const float* bh    = (const float*)d_in[6];
    const float* gamma = (const float*)d_in[7];
    float* out = (float*)d_out;

    (void)in_sizes; (void)n_in; (void)out_size;

    cudaFuncSetAttribute(pass1_kernel, cudaFuncAttributeMaxDynamicSharedMemorySize,
                         16384 * sizeof(float));
    cudaFuncSetAttribute(pass2_kernel, cudaFuncAttributeMaxDynamicSharedMemorySize,
                         41216 * sizeof(float));

    fgh_kernel<<<dim3(NPIX / 256, BATCH), 256>>>(x, Wf, bf, Wg, bg, Wh, bh);
    pass1_kernel<<<dim3(NPIX / 128, BATCH), 256, 16384 * sizeof(float)>>>();
    pass2_kernel<<<dim3(NPIX / 128, BATCH), 256, 41216 * sizeof(float)>>>(x, gamma, out);
}

// round 4
// speedup vs baseline: 2.5399x; 2.5377x over previous
#include <cuda_runtime.h>
#include <cuda_bf16.h>
#include <cstdint>

#define BATCH 8
#define CH    64
#define NPIX  4096

// Scratch (device globals; no allocations allowed). g_z stores 1/Z.
__device__ __align__(128) __nv_bfloat16 g_fhi[BATCH*NPIX*CH]; // [b][n][c]
__device__ __align__(128) __nv_bfloat16 g_flo[BATCH*NPIX*CH];
__device__ __align__(128) __nv_bfloat16 g_ghi[BATCH*NPIX*CH]; // [b][n][c]
__device__ __align__(128) __nv_bfloat16 g_glo[BATCH*NPIX*CH];
__device__ __align__(128) __nv_bfloat16 g_hhi[BATCH*CH*NPIX]; // [b][c][n]
__device__ __align__(128) __nv_bfloat16 g_hlo[BATCH*CH*NPIX];
__device__ float g_m[BATCH*NPIX];
__device__ float g_z[BATCH*NPIX];

__device__ __forceinline__ uint32_t smem_u32(const void* p){
    uint32_t a; asm("{ .reg .u64 t; cvta.to.shared.u64 t, %1; cvt.u32.u64 %0, t; }":"=r"(a):"l"(p)); return a;
}
__device__ __forceinline__ uint32_t swz(uint32_t o){ return o ^ ((o>>3)&0x70); }   // 128B rows
__device__ __forceinline__ uint32_t swzH(uint32_t o){ return o ^ ((o>>4)&0x70); }  // 256B rows
__device__ __forceinline__ uint32_t pack2(__nv_bfloat16 a, __nv_bfloat16 b){
    __nv_bfloat162 t; t.x=a; t.y=b; return *reinterpret_cast<uint32_t*>(&t);
}
#define CP16(dst, src) asm volatile("cp.async.cg.shared.global [%0], [%1], 16;"::"r"(dst),"l"(src):"memory")
#define CPCOMMIT()     asm volatile("cp.async.commit_group;":::"memory")
#define CPWAIT(n)      asm volatile("cp.async.wait_group %0;"::"n"(n):"memory")

__device__ __forceinline__ void ldsm4(uint32_t r[4], uint32_t addr){
    asm volatile("ldmatrix.sync.aligned.m8n8.x4.shared.b16 {%0,%1,%2,%3},[%4];"
        : "=r"(r[0]),"=r"(r[1]),"=r"(r[2]),"=r"(r[3]) : "r"(addr));
}
__device__ __forceinline__ void mma_bf16(float d[4], const uint32_t a[4], const uint32_t b[2]){
    asm volatile("mma.sync.aligned.m16n8k16.row.col.f32.bf16.bf16.f32 "
        "{%0,%1,%2,%3},{%4,%5,%6,%7},{%8,%9},{%0,%1,%2,%3};"
        : "+f"(d[0]),"+f"(d[1]),"+f"(d[2]),"+f"(d[3])
        : "r"(a[0]),"r"(a[1]),"r"(a[2]),"r"(a[3]),"r"(b[0]),"r"(b[1]));
}

// ---------------- Stage A: projections + hi/lo split ------------------------
__global__ __launch_bounds__(256) void fgh_split(
    const float* __restrict__ x,
    const float* __restrict__ Wf, const float* __restrict__ bf,
    const float* __restrict__ Wg, const float* __restrict__ bg,
    const float* __restrict__ Wh, const float* __restrict__ bh)
{
    __shared__ float sW[CH*CH];
    __shared__ float sb[CH];
    const int b = blockIdx.y, mtx = blockIdx.z;
    const int n = blockIdx.x*256 + threadIdx.x;
    const float* W = (mtx==0)?Wf:((mtx==1)?Wg:Wh);
    const float* bias = (mtx==0)?bf:((mtx==1)?bg:bh);
    for (int q = threadIdx.x; q < CH*CH; q += 256) sW[q] = W[q];
    if (threadIdx.x < CH) sb[threadIdx.x] = bias[threadIdx.x];
    float xc[CH];
    const float* xb = x + (size_t)b*CH*NPIX + n;
#pragma unroll
    for (int c = 0; c < CH; c++) xc[c] = xb[(size_t)c*NPIX];
    __syncthreads();

    if (mtx < 2) {
        uint32_t* hi2 = (uint32_t*)((mtx==0?g_fhi:g_ghi) + ((size_t)b*NPIX+n)*CH);
        uint32_t* lo2 = (uint32_t*)((mtx==0?g_flo:g_glo) + ((size_t)b*NPIX+n)*CH);
        for (int o2 = 0; o2 < CH/2; o2++) {
            float v0 = sb[2*o2], v1 = sb[2*o2+1];
            const float4* w0 = (const float4*)(sW + (2*o2)*CH);
            const float4* w1 = (const float4*)(sW + (2*o2+1)*CH);
#pragma unroll
            for (int c4 = 0; c4 < CH/4; c4++) {
                float4 a = w0[c4], bb = w1[c4];
                v0 += a.x*xc[c4*4] + a.y*xc[c4*4+1] + a.z*xc[c4*4+2] + a.w*xc[c4*4+3];
                v1 += bb.x*xc[c4*4] + bb.y*xc[c4*4+1] + bb.z*xc[c4*4+2] + bb.w*xc[c4*4+3];
            }
            __nv_bfloat16 h0=__float2bfloat16(v0), h1=__float2bfloat16(v1);
            hi2[o2] = pack2(h0,h1);
            lo2[o2] = pack2(__float2bfloat16(v0-__bfloat162float(h0)),
                            __float2bfloat16(v1-__bfloat162float(h1)));
        }
    } else {
        __nv_bfloat16* hh = g_hhi + (size_t)b*CH*NPIX + n;
        __nv_bfloat16* hl = g_hlo + (size_t)b*CH*NPIX + n;
        for (int o = 0; o < CH; o++) {
            float v = sb[o];
            const float4* w = (const float4*)(sW + o*CH);
#pragma unroll
            for (int c4 = 0; c4 < CH/4; c4++) {
                float4 a = w[c4];
                v += a.x*xc[c4*4] + a.y*xc[c4*4+1] + a.z*xc[c4*4+2] + a.w*xc[c4*4+3];
            }
            __nv_bfloat16 h0 = __float2bfloat16(v);
            hh[(size_t)o*NPIX] = h0;
            hl[(size_t)o*NPIX] = __float2bfloat16(v-__bfloat162float(h0));
        }
    }
}

// ---------------- Pass 1: m[i], 1/Z[i] via HMMA ------------------------------
// grid (32, 8), 256 threads (8 warps x 16 i-rows). smem 96KB (+align pad).
__global__ __launch_bounds__(256,1) void pass1_hmma()
{
    extern __shared__ uint8_t dyn1[];
    uint8_t* A = (uint8_t*)(((uintptr_t)dyn1 + 1023) & ~(uintptr_t)1023);
    const uint32_t Au = smem_u32(A);
    const uint32_t FH=0, FL=16384, GB=32768;  // g buffers: GB + buf*32768 (+0 hi, +16384 lo)

    const int t = threadIdx.x, lane = t&31, wid = t>>5;
    const int b = blockIdx.y, i0 = blockIdx.x*128;

    { // f tile loads
        const char* fh = (const char*)(g_fhi + ((size_t)b*NPIX+i0)*CH);
        const char* fl = (const char*)(g_flo + ((size_t)b*NPIX+i0)*CH);
        for (int q = t; q < 1024; q += 256) CP16(Au+FH+swz(q*16), fh + q*16);
        for (int q = t; q < 1024; q += 256) CP16(Au+FL+swz(q*16), fl + q*16);
        CPCOMMIT();
    }
#pragma unroll 1
    for (int pre = 0; pre < 2; pre++) {  // g tiles 0,1
        const char* gh = (const char*)(g_ghi + ((size_t)b*NPIX + pre*128)*CH);
        const char* gl = (const char*)(g_glo + ((size_t)b*NPIX + pre*128)*CH);
        uint32_t base = Au + GB + pre*32768;
        for (int q = t; q < 1024; q += 256) CP16(base+swz(q*16),       gh + q*16);
        for (int q = t; q < 1024; q += 256) CP16(base+16384+swz(q*16), gl + q*16);
        CPCOMMIT();
    }
    CPWAIT(2); __syncthreads();

    // preload f A-frags
    uint32_t afh[4][4], afl[4][4];
#pragma unroll
    for (int kk = 0; kk < 4; kk++) {
        uint32_t off = swz((uint32_t)((wid*16 + (lane&15))*128 + kk*32 + ((lane>>4)&1)*16));
        ldsm4(afh[kk], Au+FH+off);
        ldsm4(afl[kk], Au+FL+off);
    }

    float m0=-1e30f, m1=-1e30f, z0=0.f, z1=0.f;

#pragma unroll 1
    for (int jt = 0; jt < 32; jt++) {
        CPWAIT(1); __syncthreads();
        uint32_t gb = Au + GB + (uint32_t)(jt&1)*32768;

        float acc[16][4];
#pragma unroll
        for (int nb = 0; nb < 16; nb++) { acc[nb][0]=0.f; acc[nb][1]=0.f; acc[nb][2]=0.f; acc[nb][3]=0.f; }

#pragma unroll
        for (int kk = 0; kk < 4; kk++) {
#pragma unroll
            for (int p = 0; p < 8; p++) {
                uint32_t off = swz((uint32_t)((p*16 + ((lane>>4)&1)*8 + (lane&7))*128
                                              + kk*32 + ((lane>>3)&1)*16));
                uint32_t bh[4], bl[4];
                ldsm4(bh, gb+off);
                ldsm4(bl, gb+16384+off);
                mma_bf16(acc[2*p],   afh[kk], &bh[0]);
                mma_bf16(acc[2*p],   afh[kk], &bl[0]);
                mma_bf16(acc[2*p],   afl[kk], &bh[0]);
                mma_bf16(acc[2*p+1], afh[kk], &bh[2]);
                mma_bf16(acc[2*p+1], afh[kk], &bl[2]);
                mma_bf16(acc[2*p+1], afl[kk], &bh[2]);
            }
        }

        // online softmax: row0 = acc[nb][0,1], row1 = acc[nb][2,3]; quad spans all 128 j
        float ml0=-1e30f, ml1=-1e30f;
#pragma unroll
        for (int nb = 0; nb < 16; nb++) {
            ml0 = fmaxf(ml0, fmaxf(acc[nb][0], acc[nb][1]));
            ml1 = fmaxf(ml1, fmaxf(acc[nb][2], acc[nb][3]));
        }
        ml0 = fmaxf(ml0, __shfl_xor_sync(0xFFFFFFFFu, ml0, 1));
        ml0 = fmaxf(ml0, __shfl_xor_sync(0xFFFFFFFFu, ml0, 2));
        ml1 = fmaxf(ml1, __shfl_xor_sync(0xFFFFFFFFu, ml1, 1));
        ml1 = fmaxf(ml1, __shfl_xor_sync(0xFFFFFFFFu, ml1, 2));
        float n0 = fmaxf(m0, ml0), n1 = fmaxf(m1, ml1);
        float s0 = 0.f, s1 = 0.f;
#pragma unroll
        for (int nb = 0; nb < 16; nb++) {
            s0 += __expf(acc[nb][0]-n0) + __expf(acc[nb][1]-n0);
            s1 += __expf(acc[nb][2]-n1) + __expf(acc[nb][3]-n1);
        }
        s0 += __shfl_xor_sync(0xFFFFFFFFu, s0, 1);
        s0 += __shfl_xor_sync(0xFFFFFFFFu, s0, 2);
        s1 += __shfl_xor_sync(0xFFFFFFFFu, s1, 1);
        s1 += __shfl_xor_sync(0xFFFFFFFFu, s1, 2);
        z0 = z0*__expf(m0-n0) + s0;  m0 = n0;
        z1 = z1*__expf(m1-n1) + s1;  m1 = n1;

        __syncthreads();
        if (jt+2 < 32) {
            const char* gh = (const char*)(g_ghi + ((size_t)b*NPIX + (jt+2)*128)*CH);
            const char* gl = (const char*)(g_glo + ((size_t)b*NPIX + (jt+2)*128)*CH);
            uint32_t base = Au + GB + (uint32_t)(jt&1)*32768;
            for (int q = t; q < 1024; q += 256) CP16(base+swz(q*16),       gh + q*16);
            for (int q = t; q < 1024; q += 256) CP16(base+16384+swz(q*16), gl + q*16);
        }
        CPCOMMIT();
    }

    if ((lane&3) == 0) {
        int r = b*NPIX + i0 + wid*16 + (lane>>2);
        g_m[r]   = m0;  g_z[r]   = 1.0f/z0;
        g_m[r+8] = m1;  g_z[r+8] = 1.0f/z1;
    }
}

// ---------------- Pass 2: out'[j,c] via HMMA ---------------------------------
// grid (32, 8), 256 threads. smem = g tile 32KB + 2 x 65KB buffers (f,h,m,rz).
#define BUFST 66560u
__global__ __launch_bounds__(256,1) void pass2_hmma(
    const float* __restrict__ x, const float* __restrict__ gamma,
    float* __restrict__ out)
{
    extern __shared__ uint8_t dyn2[];
    uint8_t* A = (uint8_t*)(((uintptr_t)dyn2 + 1023) & ~(uintptr_t)1023);
    const uint32_t Au = smem_u32(A);
    const uint32_t GTH=0, GTL=16384, B0=32768;
    const uint32_t FH=0, FL=16384, HH=32768, HL=49152, MS=65536, RZ=66048;

    const int t = threadIdx.x, lane = t&31, wid = t>>5;
    const int b = blockIdx.y, j0 = blockIdx.x*128;

    { // fixed g tile (A operand rows j)
        const char* gh = (const char*)(g_ghi + ((size_t)b*NPIX+j0)*CH);
        const char* gl = (const char*)(g_glo + ((size_t)b*NPIX+j0)*CH);
        for (int q = t; q < 1024; q += 256) CP16(Au+GTH+swz(q*16), gh + q*16);
        for (int q = t; q < 1024; q += 256) CP16(Au+GTL+swz(q*16), gl + q*16);
        CPCOMMIT();
    }
#pragma unroll 1
    for (int pre = 0; pre < 2; pre++) {  // i-tiles 0,1
        const int i0 = pre*128;
        uint32_t base = Au + B0 + pre*BUFST;
        const char* fh = (const char*)(g_fhi + ((size_t)b*NPIX+i0)*CH);
        const char* fl = (const char*)(g_flo + ((size_t)b*NPIX+i0)*CH);
        for (int q = t; q < 1024; q += 256) CP16(base+FH+swz(q*16), fh + q*16);
        for (int q = t; q < 1024; q += 256) CP16(base+FL+swz(q*16), fl + q*16);
        const char* hh = (const char*)(g_hhi + (size_t)b*CH*NPIX + i0);
        const char* hl = (const char*)(g_hlo + (size_t)b*CH*NPIX + i0);
        for (int q = t; q < 1024; q += 256) {
            uint32_t roff = (uint32_t)(q>>4)*NPIX*2 + (uint32_t)(q&15)*16;
            CP16(base+HH+swzH(q*16), hh + roff);
            CP16(base+HL+swzH(q*16), hl + roff);
        }
        if (t < 32)            CP16(base+MS + t*16,      (const char*)(g_m + b*NPIX + i0) + t*16);
        else if (t < 64)       CP16(base+RZ + (t-32)*16, (const char*)(g_z + b*NPIX + i0) + (t-32)*16);
        CPCOMMIT();
    }
    CPWAIT(2); __syncthreads();

    // preload g A-frags
    uint32_t agh[4][4], agl[4][4];
#pragma unroll
    for (int kk = 0; kk < 4; kk++) {
        uint32_t off = swz((uint32_t)((wid*16 + (lane&15))*128 + kk*32 + ((lane>>4)&1)*16));
        ldsm4(agh[kk], Au+GTH+off);
        ldsm4(agl[kk], Au+GTL+off);
    }

    float oacc[8][4];
#pragma unroll
    for (int nb = 0; nb < 8; nb++) { oacc[nb][0]=0.f; oacc[nb][1]=0.f; oacc[nb][2]=0.f; oacc[nb][3]=0.f; }

#pragma unroll 1
    for (int it = 0; it < 32; it++) {
        CPWAIT(1); __syncthreads();
        uint32_t bb = Au + B0 + (uint32_t)(it&1)*BUFST;
        const float* msp = (const float*)(A + (B0 - 0) + (it&1)*BUFST + MS);
        const float* rzp = (const float*)(A + (B0 - 0) + (it&1)*BUFST + RZ);

        // GEMM1': S'[j(16/warp), i(128)] = g . f^T (3-term split)
        float sacc[16][4];
#pragma unroll
        for (int nb = 0; nb < 16; nb++) { sacc[nb][0]=0.f; sacc[nb][1]=0.f; sacc[nb][2]=0.f; sacc[nb][3]=0.f; }
#pragma unroll
        for (int kk = 0; kk < 4; kk++) {
#pragma unroll
            for (int p = 0; p < 8; p++) {
                uint32_t off = swz((uint32_t)((p*16 + ((lane>>4)&1)*8 + (lane&7))*128
                                              + kk*32 + ((lane>>3)&1)*16));
                uint32_t bh[4], bl[4];
                ldsm4(bh, bb+FH+off);
                ldsm4(bl, bb+FL+off);
                mma_bf16(sacc[2*p],   agh[kk], &bh[0]);
                mma_bf16(sacc[2*p],   agh[kk], &bl[0]);
                mma_bf16(sacc[2*p],   agl[kk], &bh[0]);
                mma_bf16(sacc[2*p+1], agh[kk], &bh[2]);
                mma_bf16(sacc[2*p+1], agh[kk], &bl[2]);
                mma_bf16(sacc[2*p+1], agl[kk], &bh[2]);
            }
        }

        // per k-chunk: convert S'->P' (exp * 1/Z, split bf16), then GEMM2 mmas
#pragma unroll
        for (int kk = 0; kk < 8; kk++) {
            uint32_t aH[4], aL[4];
#pragma unroll
            for (int u = 0; u < 2; u++) {
                int nb = 2*kk + u;
                int ic = nb*8 + (lane&3)*2;
                float m0v = msp[ic], m1v = msp[ic+1];
                float r0v = rzp[ic], r1v = rzp[ic+1];
                float p00 = __expf(sacc[nb][0]-m0v)*r0v;
                float p01 = __expf(sacc[nb][1]-m1v)*r1v;
                float p10 = __expf(sacc[nb][2]-m0v)*r0v;
                float p11 = __expf(sacc[nb][3]-m1v)*r1v;
                __nv_bfloat16 h00=__float2bfloat16(p00), h01=__float2bfloat16(p01);
                __nv_bfloat16 h10=__float2bfloat16(p10), h11=__float2bfloat16(p11);
                aH[0+u*2] = pack2(h00,h01);
                aH[1+u*2] = pack2(h10,h11);
                aL[0+u*2] = pack2(__float2bfloat16(p00-__bfloat162float(h00)),
                                  __float2bfloat16(p01-__bfloat162float(h01)));
                aL[1+u*2] = pack2(__float2bfloat16(p10-__bfloat162float(h10)),
                                  __float2bfloat16(p11-__bfloat162float(h11)));
            }
#pragma unroll
            for (int p = 0; p < 4; p++) {
                uint32_t off = swzH((uint32_t)((p*16 + ((lane>>4)&1)*8 + (lane&7))*256
                                               + kk*32 + ((lane>>3)&1)*16));
                uint32_t bh[4], bl[4];
                ldsm4(bh, bb+HH+off);
                ldsm4(bl, bb+HL+off);
                mma_bf16(oacc[2*p],   aH, &bh[0]);
                mma_bf16(oacc[2*p],   aH, &bl[0]);
                mma_bf16(oacc[2*p],   aL, &bh[0]);
                mma_bf16(oacc[2*p+1], aH, &bh[2]);
                mma_bf16(oacc[2*p+1], aH, &bl[2]);
                mma_bf16(oacc[2*p+1], aL, &bh[2]);
            }
        }

        __syncthreads();
        if (it+2 < 32) {
            const int i0 = (it+2)*128;
            uint32_t base = Au + B0 + (uint32_t)(it&1)*BUFST;
            const char* fh = (const char*)(g_fhi + ((size_t)b*NPIX+i0)*CH);
            const char* fl = (const char*)(g_flo + ((size_t)b*NPIX+i0)*CH);
            for (int q = t; q < 1024; q += 256) CP16(base+FH+swz(q*16), fh + q*16);
            for (int q = t; q < 1024; q += 256) CP16(base+FL+swz(q*16), fl + q*16);
            const char* hh = (const char*)(g_hhi + (size_t)b*CH*NPIX + i0);
            const char* hl = (const char*)(g_hlo + (size_t)b*CH*NPIX + i0);
            for (int q = t; q < 1024; q += 256) {
                uint32_t roff = (uint32_t)(q>>4)*NPIX*2 + (uint32_t)(q&15)*16;
                CP16(base+HH+swzH(q*16), hh + roff);
                CP16(base+HL+swzH(q*16), hl + roff);
            }
            if (t < 32)      CP16(base+MS + t*16,      (const char*)(g_m + b*NPIX + i0) + t*16);
            else if (t < 64) CP16(base+RZ + (t-32)*16, (const char*)(g_z + b*NPIX + i0) + (t-32)*16);
        }
        CPCOMMIT();
    }

    // epilogue: thread holds out'[j, c]; j = j0 + wid*16 + lane>>2 (+8), c = nb*8+(lane&3)*2 (+1)
    const float gam = *gamma;
    const int jr = j0 + wid*16 + (lane>>2);
#pragma unroll
    for (int nb = 0; nb < 8; nb++) {
        int c0 = nb*8 + (lane&3)*2;
        size_t o0 = ((size_t)b*CH + c0)*NPIX;
        size_t o1 = ((size_t)b*CH + c0 + 1)*NPIX;
        out[o0 + jr]     = gam*oacc[nb][0] + x[o0 + jr];
        out[o1 + jr]     = gam*oacc[nb][1] + x[o1 + jr];
        out[o0 + jr + 8] = gam*oacc[nb][2] + x[o0 + jr + 8];
        out[o1 + jr + 8] = gam*oacc[nb][3] + x[o1 + jr + 8];
    }
}

// -----------------------------------------------------------------------------
extern "C" void kernel_launch(void* const* d_in, const int* in_sizes, int n_in,
                              void* d_out, int out_size)
{
    const float* x     = (const float*)d_in[0];
    const float* Wf    = (const float*)d_in[1];
    const float* bf    = (const float*)d_in[2];
    const float* Wg    = (const float*)d_in[3];
    const float* bg    = (const float*)d_in[4];
    const float* Wh    = (const float*)d_in[5];
    const float* bh    = (const float*)d_in[6];
    const float* gamma = (const float*)d_in[7];
    float* out = (float*)d_out;
    (void)in_sizes; (void)n_in; (void)out_size;

    cudaFuncSetAttribute(pass1_hmma, cudaFuncAttributeMaxDynamicSharedMemorySize, 98304+1024);
    cudaFuncSetAttribute(pass2_hmma, cudaFuncAttributeMaxDynamicSharedMemorySize, 32768+2*66560+1024);

    fgh_split<<<dim3(NPIX/256, BATCH, 3), 256>>>(x, Wf, bf, Wg, bg, Wh, bh);
    pass1_hmma<<<dim3(32, BATCH), 256, 98304+1024>>>();
    pass2_hmma<<<dim3(32, BATCH), 256, 32768+2*66560+1024>>>(x, gamma, out);
}

// round 5
// speedup vs baseline: 3.5135x; 1.3833x over previous
#include <cuda_runtime.h>
#include <cuda_fp16.h>
#include <cstdint>

#define BATCH 8
#define CH    64
#define NPIX  4096

// Scratch (device globals). g_z stores 1/Z.
__device__ __align__(128) __half g_fh[BATCH*NPIX*CH]; // f hi  [b][n][c]
__device__ __align__(128) __half g_fl[BATCH*NPIX*CH]; // f lo
__device__ __align__(128) __half g_gq[BATCH*NPIX*CH]; // g single [b][n][c]
__device__ __align__(128) __half g_hq[BATCH*CH*NPIX]; // h single [b][c][n]
__device__ float g_m[BATCH*NPIX];
__device__ float g_z[BATCH*NPIX];

__device__ __forceinline__ uint32_t smem_u32(const void* p){
    uint32_t a; asm("{ .reg .u64 t; cvta.to.shared.u64 t, %1; cvt.u32.u64 %0, t; }":"=r"(a):"l"(p)); return a;
}
__device__ __forceinline__ uint32_t swz(uint32_t o){ return o ^ ((o>>3)&0x70); }   // 128B rows
__device__ __forceinline__ uint32_t pack2h(__half a, __half b){
    __half2 t; t.x=a; t.y=b; return *reinterpret_cast<uint32_t*>(&t);
}
#define CP16(dst, src) asm volatile("cp.async.cg.shared.global [%0], [%1], 16;"::"r"(dst),"l"(src):"memory")
#define CPCOMMIT()     asm volatile("cp.async.commit_group;":::"memory")
#define CPWAIT(n)      asm volatile("cp.async.wait_group %0;"::"n"(n):"memory")

__device__ __forceinline__ void ldsm4(uint32_t r[4], uint32_t addr){
    asm volatile("ldmatrix.sync.aligned.m8n8.x4.shared.b16 {%0,%1,%2,%3},[%4];"
        : "=r"(r[0]),"=r"(r[1]),"=r"(r[2]),"=r"(r[3]) : "r"(addr));
}
__device__ __forceinline__ void mma_f16(float d[4], const uint32_t a[4], const uint32_t b[2]){
    asm volatile("mma.sync.aligned.m16n8k16.row.col.f32.f16.f16.f32 "
        "{%0,%1,%2,%3},{%4,%5,%6,%7},{%8,%9},{%0,%1,%2,%3};"
        : "+f"(d[0]),"+f"(d[1]),"+f"(d[2]),"+f"(d[3])
        : "r"(a[0]),"r"(a[1]),"r"(a[2]),"r"(a[3]),"r"(b[0]),"r"(b[1]));
}

// ---------------- Stage A: projections + fp16 quantize ----------------------
__global__ __launch_bounds__(256) void fgh_split(
    const float* __restrict__ x,
    const float* __restrict__ Wf, const float* __restrict__ bf,
    const float* __restrict__ Wg, const float* __restrict__ bg,
    const float* __restrict__ Wh, const float* __restrict__ bh)
{
    __shared__ float sW[CH*CH];
    __shared__ float sb[CH];
    const int b = blockIdx.y, mtx = blockIdx.z;
    const int n = blockIdx.x*256 + threadIdx.x;
    const float* W = (mtx==0)?Wf:((mtx==1)?Wg:Wh);
    const float* bias = (mtx==0)?bf:((mtx==1)?bg:bh);
    for (int q = threadIdx.x; q < CH*CH; q += 256) sW[q] = W[q];
    if (threadIdx.x < CH) sb[threadIdx.x] = bias[threadIdx.x];
    float xc[CH];
    const float* xb = x + (size_t)b*CH*NPIX + n;
#pragma unroll
    for (int c = 0; c < CH; c++) xc[c] = xb[(size_t)c*NPIX];
    __syncthreads();

    if (mtx < 2) {
        uint32_t* o_hi = (uint32_t*)((mtx==0?g_fh:g_gq) + ((size_t)b*NPIX+n)*CH);
        uint32_t* o_lo = (uint32_t*)(g_fl + ((size_t)b*NPIX+n)*CH);
        for (int o2 = 0; o2 < CH/2; o2++) {
            // two independent chains per channel (break serial FMA dependency)
            float v0a = sb[2*o2], v0b = 0.f, v1a = sb[2*o2+1], v1b = 0.f;
            const float4* w0 = (const float4*)(sW + (2*o2)*CH);
            const float4* w1 = (const float4*)(sW + (2*o2+1)*CH);
#pragma unroll
            for (int c8 = 0; c8 < 8; c8++) {
                float4 a0 = w0[2*c8], a1 = w0[2*c8+1];
                float4 b0 = w1[2*c8], b1 = w1[2*c8+1];
                v0a += a0.x*xc[c8*8+0] + a0.y*xc[c8*8+1] + a0.z*xc[c8*8+2] + a0.w*xc[c8*8+3];
                v0b += a1.x*xc[c8*8+4] + a1.y*xc[c8*8+5] + a1.z*xc[c8*8+6] + a1.w*xc[c8*8+7];
                v1a += b0.x*xc[c8*8+0] + b0.y*xc[c8*8+1] + b0.z*xc[c8*8+2] + b0.w*xc[c8*8+3];
                v1b += b1.x*xc[c8*8+4] + b1.y*xc[c8*8+5] + b1.z*xc[c8*8+6] + b1.w*xc[c8*8+7];
            }
            float v0 = v0a+v0b, v1 = v1a+v1b;
            __half h0 = __float2half_rn(v0), h1 = __float2half_rn(v1);
            o_hi[o2] = pack2h(h0, h1);
            if (mtx == 0)
                o_lo[o2] = pack2h(__float2half_rn(v0-__half2float(h0)),
                                  __float2half_rn(v1-__half2float(h1)));
        }
    } else {
        __half* hq = g_hq + (size_t)b*CH*NPIX + n;
        for (int o = 0; o < CH; o++) {
            float va = sb[o], vb = 0.f;
            const float4* w = (const float4*)(sW + o*CH);
#pragma unroll
            for (int c8 = 0; c8 < 8; c8++) {
                float4 a0 = w[2*c8], a1 = w[2*c8+1];
                va += a0.x*xc[c8*8+0] + a0.y*xc[c8*8+1] + a0.z*xc[c8*8+2] + a0.w*xc[c8*8+3];
                vb += a1.x*xc[c8*8+4] + a1.y*xc[c8*8+5] + a1.z*xc[c8*8+6] + a1.w*xc[c8*8+7];
            }
            hq[(size_t)o*NPIX] = __float2half_rn(va+vb);
        }
    }
}

// ---------------- Pass 1: m[i], 1/Z[i] --------------------------------------
// grid (32, 8), 256 threads. smem: fh 16K | fl 16K | g dbl 2x16K = 64K.
__global__ __launch_bounds__(256,2) void pass1_hmma()
{
    extern __shared__ uint8_t dyn1[];
    uint8_t* A = (uint8_t*)(((uintptr_t)dyn1 + 1023) & ~(uintptr_t)1023);
    const uint32_t Au = smem_u32(A);
    const uint32_t FH=0, FL=16384, GB=32768;

    const int t = threadIdx.x, lane = t&31, wid = t>>5;
    const int b = blockIdx.y, i0 = blockIdx.x*128;

    { // f tiles [128 i][64 c]
        const char* fh = (const char*)(g_fh + ((size_t)b*NPIX+i0)*CH);
        const char* fl = (const char*)(g_fl + ((size_t)b*NPIX+i0)*CH);
        for (int q = t; q < 1024; q += 256) CP16(Au+FH+swz(q*16), fh + q*16);
        for (int q = t; q < 1024; q += 256) CP16(Au+FL+swz(q*16), fl + q*16);
        CPCOMMIT();
    }
#pragma unroll 1
    for (int pre = 0; pre < 2; pre++) {
        const char* gq = (const char*)(g_gq + ((size_t)b*NPIX + pre*128)*CH);
        uint32_t base = Au + GB + pre*16384;
        for (int q = t; q < 1024; q += 256) CP16(base+swz(q*16), gq + q*16);
        CPCOMMIT();
    }
    CPWAIT(2); __syncthreads();   // f tiles done

    uint32_t afh[4][4], afl[4][4];
#pragma unroll
    for (int kk = 0; kk < 4; kk++) {
        uint32_t off = swz((uint32_t)((wid*16 + (lane&15))*128 + kk*32 + ((lane>>4)&1)*16));
        ldsm4(afh[kk], Au+FH+off);
        ldsm4(afl[kk], Au+FL+off);
    }

    float m0=-1e30f, m1=-1e30f, z0=0.f, z1=0.f;

#pragma unroll 1
    for (int jt = 0; jt < 32; jt++) {
        CPWAIT(1); __syncthreads();
        uint32_t gb = Au + GB + (uint32_t)(jt&1)*16384;

        float acc[16][4];
#pragma unroll
        for (int nb = 0; nb < 16; nb++) { acc[nb][0]=0.f; acc[nb][1]=0.f; acc[nb][2]=0.f; acc[nb][3]=0.f; }

#pragma unroll
        for (int kk = 0; kk < 4; kk++) {
#pragma unroll
            for (int p = 0; p < 8; p++) {
                uint32_t off = swz((uint32_t)((p*16 + ((lane>>4)&1)*8 + (lane&7))*128
                                              + kk*32 + ((lane>>3)&1)*16));
                uint32_t bh[4];
                ldsm4(bh, gb+off);
                mma_f16(acc[2*p],   afh[kk], &bh[0]);
                mma_f16(acc[2*p],   afl[kk], &bh[0]);
                mma_f16(acc[2*p+1], afh[kk], &bh[2]);
                mma_f16(acc[2*p+1], afl[kk], &bh[2]);
            }
        }

        float ml0=-1e30f, ml1=-1e30f;
#pragma unroll
        for (int nb = 0; nb < 16; nb++) {
            ml0 = fmaxf(ml0, fmaxf(acc[nb][0], acc[nb][1]));
            ml1 = fmaxf(ml1, fmaxf(acc[nb][2], acc[nb][3]));
        }
        ml0 = fmaxf(ml0, __shfl_xor_sync(0xFFFFFFFFu, ml0, 1));
        ml0 = fmaxf(ml0, __shfl_xor_sync(0xFFFFFFFFu, ml0, 2));
        ml1 = fmaxf(ml1, __shfl_xor_sync(0xFFFFFFFFu, ml1, 1));
        ml1 = fmaxf(ml1, __shfl_xor_sync(0xFFFFFFFFu, ml1, 2));
        float n0 = fmaxf(m0, ml0), n1 = fmaxf(m1, ml1);
        float s0 = 0.f, s1 = 0.f;
#pragma unroll
        for (int nb = 0; nb < 16; nb++) {
            s0 += __expf(acc[nb][0]-n0) + __expf(acc[nb][1]-n0);
            s1 += __expf(acc[nb][2]-n1) + __expf(acc[nb][3]-n1);
        }
        s0 += __shfl_xor_sync(0xFFFFFFFFu, s0, 1);
        s0 += __shfl_xor_sync(0xFFFFFFFFu, s0, 2);
        s1 += __shfl_xor_sync(0xFFFFFFFFu, s1, 1);
        s1 += __shfl_xor_sync(0xFFFFFFFFu, s1, 2);
        z0 = z0*__expf(m0-n0) + s0;  m0 = n0;
        z1 = z1*__expf(m1-n1) + s1;  m1 = n1;

        __syncthreads();
        if (jt+2 < 32) {
            const char* gq = (const char*)(g_gq + ((size_t)b*NPIX + (jt+2)*128)*CH);
            uint32_t base = Au + GB + (uint32_t)(jt&1)*16384;
            for (int q = t; q < 1024; q += 256) CP16(base+swz(q*16), gq + q*16);
        }
        CPCOMMIT();
    }

    if ((lane&3) == 0) {
        int r = b*NPIX + i0 + wid*16 + (lane>>2);
        g_m[r]   = m0;  g_z[r]   = 1.0f/z0;
        g_m[r+8] = m1;  g_z[r+8] = 1.0f/z1;
    }
}

// ---------------- Pass 2: out'[j,c] -----------------------------------------
// grid (32, 8), 256 threads. smem: g 16K + 2 x (f 16K + h 8K + mz 0.5K).
#define BUFST 25600u
#define B0    16384u
#define OF_FH 0u
#define OF_FL 8192u
#define OF_HH 16384u
#define OF_MZ 24576u
__global__ __launch_bounds__(256,2) void pass2_hmma(
    const float* __restrict__ x, const float* __restrict__ gamma,
    float* __restrict__ out)
{
    extern __shared__ uint8_t dyn2[];
    uint8_t* A = (uint8_t*)(((uintptr_t)dyn2 + 1023) & ~(uintptr_t)1023);
    const uint32_t Au = smem_u32(A);

    const int t = threadIdx.x, lane = t&31, wid = t>>5;
    const int b = blockIdx.y, j0 = blockIdx.x*128;

    { // fixed g tile [128 j][64 c]
        const char* gq = (const char*)(g_gq + ((size_t)b*NPIX+j0)*CH);
        for (int q = t; q < 1024; q += 256) CP16(Au+swz(q*16), gq + q*16);
        CPCOMMIT();
    }
#pragma unroll 1
    for (int pre = 0; pre < 2; pre++) { // i-tiles 0,1 (64 i each)
        const int i0 = pre*64;
        uint32_t base = Au + B0 + pre*BUFST;
        const char* fh = (const char*)(g_fh + ((size_t)b*NPIX+i0)*CH);
        const char* fl = (const char*)(g_fl + ((size_t)b*NPIX+i0)*CH);
        for (int q = t; q < 512; q += 256) { CP16(base+OF_FH+swz(q*16), fh + q*16);
                                             CP16(base+OF_FL+swz(q*16), fl + q*16); }
        const char* hq = (const char*)(g_hq + (size_t)b*CH*NPIX + i0);
        for (int q = t; q < 512; q += 256)
            CP16(base+OF_HH+swz(q*16), hq + (uint32_t)(q>>3)*NPIX*2 + (uint32_t)(q&7)*16);
        if (t < 16)       CP16(base+OF_MZ + t*16,          (const char*)(g_m + b*NPIX + i0) + t*16);
        else if (t < 32)  CP16(base+OF_MZ + 256 + (t-16)*16, (const char*)(g_z + b*NPIX + i0) + (t-16)*16);
        CPCOMMIT();
    }
    CPWAIT(2); __syncthreads();   // g tile done

    uint32_t ag[4][4];
#pragma unroll
    for (int kk = 0; kk < 4; kk++) {
        uint32_t off = swz((uint32_t)((wid*16 + (lane&15))*128 + kk*32 + ((lane>>4)&1)*16));
        ldsm4(ag[kk], Au+off);
    }

    float oacc[8][4];
#pragma unroll
    for (int nb = 0; nb < 8; nb++) { oacc[nb][0]=0.f; oacc[nb][1]=0.f; oacc[nb][2]=0.f; oacc[nb][3]=0.f; }

#pragma unroll 1
    for (int it = 0; it < 64; it++) {
        CPWAIT(1); __syncthreads();
        uint32_t bb = Au + B0 + (uint32_t)(it&1)*BUFST;
        const float* ms = (const float*)(A + B0 + (it&1)*BUFST + OF_MZ);
        const float* rz = ms + 64;

        // GEMM1': S'[16 j/warp, 64 i] = g . f^T (f split, 2-term)
        float sacc[8][4];
#pragma unroll
        for (int nb = 0; nb < 8; nb++) { sacc[nb][0]=0.f; sacc[nb][1]=0.f; sacc[nb][2]=0.f; sacc[nb][3]=0.f; }
#pragma unroll
        for (int kk = 0; kk < 4; kk++) {
#pragma unroll
            for (int p = 0; p < 4; p++) {
                uint32_t off = swz((uint32_t)((p*16 + ((lane>>4)&1)*8 + (lane&7))*128
                                              + kk*32 + ((lane>>3)&1)*16));
                uint32_t bh[4], bl[4];
                ldsm4(bh, bb+OF_FH+off);
                ldsm4(bl, bb+OF_FL+off);
                mma_f16(sacc[2*p],   ag[kk], &bh[0]);
                mma_f16(sacc[2*p],   ag[kk], &bl[0]);
                mma_f16(sacc[2*p+1], ag[kk], &bh[2]);
                mma_f16(sacc[2*p+1], ag[kk], &bl[2]);
            }
        }

        // convert S'->P' (exp * 1/Z, fp16 split) per 16-i chunk, then GEMM2
#pragma unroll
        for (int kk2 = 0; kk2 < 4; kk2++) {
            uint32_t aH[4], aL[4];
#pragma unroll
            for (int u = 0; u < 2; u++) {
                int nb = 2*kk2 + u;
                int ic = nb*8 + (lane&3)*2;
                float m0v = ms[ic], m1v = ms[ic+1];
                float r0v = rz[ic], r1v = rz[ic+1];
                float p00 = __expf(sacc[nb][0]-m0v)*r0v;
                float p01 = __expf(sacc[nb][1]-m1v)*r1v;
                float p10 = __expf(sacc[nb][2]-m0v)*r0v;
                float p11 = __expf(sacc[nb][3]-m1v)*r1v;
                __half h00=__float2half_rn(p00), h01=__float2half_rn(p01);
                __half h10=__float2half_rn(p10), h11=__float2half_rn(p11);
                aH[0+u*2] = pack2h(h00,h01);
                aH[1+u*2] = pack2h(h10,h11);
                aL[0+u*2] = pack2h(__float2half_rn(p00-__half2float(h00)),
                                   __float2half_rn(p01-__half2float(h01)));
                aL[1+u*2] = pack2h(__float2half_rn(p10-__half2float(h10)),
                                   __float2half_rn(p11-__half2float(h11)));
            }
#pragma unroll
            for (int p = 0; p < 4; p++) {
                uint32_t off = swz((uint32_t)((p*16 + ((lane>>4)&1)*8 + (lane&7))*128
                                              + kk2*32 + ((lane>>3)&1)*16));
                uint32_t bh[4];
                ldsm4(bh, bb+OF_HH+off);
                mma_f16(oacc[2*p],   aH, &bh[0]);
                mma_f16(oacc[2*p],   aL, &bh[0]);
                mma_f16(oacc[2*p+1], aH, &bh[2]);
                mma_f16(oacc[2*p+1], aL, &bh[2]);
            }
        }

        __syncthreads();
        if (it+2 < 64) {
            const int i0 = (it+2)*64;
            uint32_t base = Au + B0 + (uint32_t)(it&1)*BUFST;
            const char* fh = (const char*)(g_fh + ((size_t)b*NPIX+i0)*CH);
            const char* fl = (const char*)(g_fl + ((size_t)b*NPIX+i0)*CH);
            for (int q = t; q < 512; q += 256) { CP16(base+OF_FH+swz(q*16), fh + q*16);
                                                 CP16(base+OF_FL+swz(q*16), fl + q*16); }
            const char* hq = (const char*)(g_hq + (size_t)b*CH*NPIX + i0);
            for (int q = t; q < 512; q += 256)
                CP16(base+OF_HH+swz(q*16), hq + (uint32_t)(q>>3)*NPIX*2 + (uint32_t)(q&7)*16);
            if (t < 16)       CP16(base+OF_MZ + t*16,          (const char*)(g_m + b*NPIX + i0) + t*16);
            else if (t < 32)  CP16(base+OF_MZ + 256 + (t-16)*16, (const char*)(g_z + b*NPIX + i0) + (t-16)*16);
        }
        CPCOMMIT();
    }

    // Epilogue: stage [64 c][128 j] fp32 in smem, then coalesced gamma*o + x
    __syncthreads();
    float* outs = (float*)(A + B0);
    const int jl = wid*16 + (lane>>2);
#pragma unroll
    for (int nb = 0; nb < 8; nb++) {
        int c0 = nb*8 + (lane&3)*2;
        outs[c0*128 + jl]           = oacc[nb][0];
        outs[(c0+1)*128 + jl]       = oacc[nb][1];
        outs[c0*128 + jl + 8]       = oacc[nb][2];
        outs[(c0+1)*128 + jl + 8]   = oacc[nb][3];
    }
    __syncthreads();
    const float gam = *gamma;
    {
        const int row = t>>2, seg = t&3;     // row = channel, seg covers 32 j
        const float* xr = x   + ((size_t)b*CH + row)*NPIX + j0 + seg*32;
        float*       orow = out + ((size_t)b*CH + row)*NPIX + j0 + seg*32;
        const float4* sr = (const float4*)(outs + row*128 + seg*32);
#pragma unroll
        for (int u = 0; u < 8; u++) {
            float4 v = sr[u];
            float4 xv = *(const float4*)(xr + u*4);
            float4 r;
            r.x = gam*v.x + xv.x; r.y = gam*v.y + xv.y;
            r.z = gam*v.z + xv.z; r.w = gam*v.w + xv.w;
            *(float4*)(orow + u*4) = r;
        }
    }
}

// -----------------------------------------------------------------------------
extern "C" void kernel_launch(void* const* d_in, const int* in_sizes, int n_in,
                              void* d_out, int out_size)
{
    const float* x     = (const float*)d_in[0];
    const float* Wf    = (const float*)d_in[1];
    const float* bf    = (const float*)d_in[2];
    const float* Wg    = (const float*)d_in[3];
    const float* bg    = (const float*)d_in[4];
    const float* Wh    = (const float*)d_in[5];
    const float* bh    = (const float*)d_in[6];
    const float* gamma = (const float*)d_in[7];
    float* out = (float*)d_out;
    (void)in_sizes; (void)n_in; (void)out_size;

    cudaFuncSetAttribute(pass1_hmma, cudaFuncAttributeMaxDynamicSharedMemorySize, 65536+1024);
    cudaFuncSetAttribute(pass2_hmma, cudaFuncAttributeMaxDynamicSharedMemorySize, 16384+2*25600+1024);

    fgh_split<<<dim3(NPIX/256, BATCH, 3), 256>>>(x, Wf, bf, Wg, bg, Wh, bh);
    pass1_hmma<<<dim3(32, BATCH), 256, 65536+1024>>>();
    pass2_hmma<<<dim3(32, BATCH), 256, 16384+2*25600+1024>>>(x, gamma, out);
}

// round 6
// speedup vs baseline: 5.8307x; 1.6595x over previous
#include <cuda_runtime.h>
#include <cuda_fp16.h>
#include <cstdint>

#define BATCH 8
#define CH    64
#define NPIX  4096

// Scratch. f is pre-scaled by log2(e); g_z stores 1/Z.
__device__ __align__(128) __half g_fq[BATCH*NPIX*CH]; // f*log2e [b][n][c]
__device__ __align__(128) __half g_gq[BATCH*NPIX*CH]; // g       [b][n][c]
__device__ __align__(128) __half g_hq[BATCH*CH*NPIX]; // h       [b][c][n]
__device__ float g_z[BATCH*NPIX];

__device__ __forceinline__ uint32_t smem_u32(const void* p){
    uint32_t a; asm("{ .reg .u64 t; cvta.to.shared.u64 t, %1; cvt.u32.u64 %0, t; }":"=r"(a):"l"(p)); return a;
}
__device__ __forceinline__ uint32_t swz(uint32_t o){ return o ^ ((o>>3)&0x70); }
__device__ __forceinline__ uint32_t pack2h(__half a, __half b){
    __half2 t; t.x=a; t.y=b; return *reinterpret_cast<uint32_t*>(&t);
}
__device__ __forceinline__ float ex2(float x){
    float y; asm("ex2.approx.f32 %0, %1;":"=f"(y):"f"(x)); return y;
}
#define CP16(dst, src) asm volatile("cp.async.cg.shared.global [%0], [%1], 16;"::"r"(dst),"l"(src):"memory")
#define CPCOMMIT()     asm volatile("cp.async.commit_group;":::"memory")
#define CPWAIT(n)      asm volatile("cp.async.wait_group %0;"::"n"(n):"memory")

__device__ __forceinline__ void ldsm4(uint32_t r[4], uint32_t addr){
    asm volatile("ldmatrix.sync.aligned.m8n8.x4.shared.b16 {%0,%1,%2,%3},[%4];"
        : "=r"(r[0]),"=r"(r[1]),"=r"(r[2]),"=r"(r[3]) : "r"(addr));
}
__device__ __forceinline__ void mma_f16(float d[4], const uint32_t a[4], const uint32_t b[2]){
    asm volatile("mma.sync.aligned.m16n8k16.row.col.f32.f16.f16.f32 "
        "{%0,%1,%2,%3},{%4,%5,%6,%7},{%8,%9},{%0,%1,%2,%3};"
        : "+f"(d[0]),"+f"(d[1]),"+f"(d[2]),"+f"(d[3])
        : "r"(a[0]),"r"(a[1]),"r"(a[2]),"r"(a[3]),"r"(b[0]),"r"(b[1]));
}

// ---------------- Stage A: projections, fp16 quantize (f scaled by log2e) ---
__global__ __launch_bounds__(128) void fgh_proj(
    const float* __restrict__ x,
    const float* __restrict__ Wf, const float* __restrict__ bf,
    const float* __restrict__ Wg, const float* __restrict__ bg,
    const float* __restrict__ Wh, const float* __restrict__ bh)
{
    __shared__ float sW[CH*CH];
    __shared__ float sb[CH];
    const int b = blockIdx.y, mtx = blockIdx.z;
    const int n = blockIdx.x*128 + threadIdx.x;
    const float* W = (mtx==0)?Wf:((mtx==1)?Wg:Wh);
    const float* bias = (mtx==0)?bf:((mtx==1)?bg:bh);
    for (int q = threadIdx.x; q < CH*CH; q += 128) sW[q] = W[q];
    if (threadIdx.x < CH) sb[threadIdx.x] = bias[threadIdx.x];
    float xc[CH];
    const float* xb = x + (size_t)b*CH*NPIX + n;
#pragma unroll
    for (int c = 0; c < CH; c++) xc[c] = xb[(size_t)c*NPIX];
    __syncthreads();

    if (mtx < 2) {
        const float scale = (mtx==0) ? 1.44269504f : 1.0f;
        uint32_t* dst = (uint32_t*)((mtx==0?g_fq:g_gq) + ((size_t)b*NPIX+n)*CH);
        for (int o2 = 0; o2 < CH/2; o2++) {
            float v0a = sb[2*o2], v0b = 0.f, v1a = sb[2*o2+1], v1b = 0.f;
            const float4* w0 = (const float4*)(sW + (2*o2)*CH);
            const float4* w1 = (const float4*)(sW + (2*o2+1)*CH);
#pragma unroll
            for (int c8 = 0; c8 < 8; c8++) {
                float4 a0 = w0[2*c8], a1 = w0[2*c8+1];
                float4 b0 = w1[2*c8], b1 = w1[2*c8+1];
                v0a += a0.x*xc[c8*8+0] + a0.y*xc[c8*8+1] + a0.z*xc[c8*8+2] + a0.w*xc[c8*8+3];
                v0b += a1.x*xc[c8*8+4] + a1.y*xc[c8*8+5] + a1.z*xc[c8*8+6] + a1.w*xc[c8*8+7];
                v1a += b0.x*xc[c8*8+0] + b0.y*xc[c8*8+1] + b0.z*xc[c8*8+2] + b0.w*xc[c8*8+3];
                v1b += b1.x*xc[c8*8+4] + b1.y*xc[c8*8+5] + b1.z*xc[c8*8+6] + b1.w*xc[c8*8+7];
            }
            dst[o2] = pack2h(__float2half_rn((v0a+v0b)*scale),
                             __float2half_rn((v1a+v1b)*scale));
        }
    } else {
        __half* hq = g_hq + (size_t)b*CH*NPIX + n;
        for (int o = 0; o < CH; o++) {
            float va = sb[o], vb = 0.f;
            const float4* w = (const float4*)(sW + o*CH);
#pragma unroll
            for (int c8 = 0; c8 < 8; c8++) {
                float4 a0 = w[2*c8], a1 = w[2*c8+1];
                va += a0.x*xc[c8*8+0] + a0.y*xc[c8*8+1] + a0.z*xc[c8*8+2] + a0.w*xc[c8*8+3];
                vb += a1.x*xc[c8*8+4] + a1.y*xc[c8*8+5] + a1.z*xc[c8*8+6] + a1.w*xc[c8*8+7];
            }
            hq[(size_t)o*NPIX] = __float2half_rn(va+vb);
        }
    }
}

// ---------------- Pass 1: 1/Z[i] (no max; direct exp2 sum) ------------------
// grid (32, 8), 256 threads. smem: F 16K | G dbl 2x16K = 48K.
__global__ __launch_bounds__(256,2) void pass1_hmma()
{
    extern __shared__ uint8_t dyn1[];
    uint8_t* A = (uint8_t*)(((uintptr_t)dyn1 + 1023) & ~(uintptr_t)1023);
    const uint32_t Au = smem_u32(A);
    const uint32_t FQ=0, GB=16384;

    const int t = threadIdx.x, lane = t&31, wid = t>>5;
    const int b = blockIdx.y, i0 = blockIdx.x*128;

    {
        const char* fq = (const char*)(g_fq + ((size_t)b*NPIX+i0)*CH);
        for (int q = t; q < 1024; q += 256) CP16(Au+FQ+swz(q*16), fq + q*16);
        CPCOMMIT();
    }
#pragma unroll 1
    for (int pre = 0; pre < 2; pre++) {
        const char* gq = (const char*)(g_gq + ((size_t)b*NPIX + pre*128)*CH);
        uint32_t base = Au + GB + pre*16384;
        for (int q = t; q < 1024; q += 256) CP16(base+swz(q*16), gq + q*16);
        CPCOMMIT();
    }
    CPWAIT(2); __syncthreads();

    uint32_t af[4][4];
#pragma unroll
    for (int kk = 0; kk < 4; kk++) {
        uint32_t off = swz((uint32_t)((wid*16 + (lane&15))*128 + kk*32 + ((lane>>4)&1)*16));
        ldsm4(af[kk], Au+FQ+off);
    }

    float z0 = 0.f, z1 = 0.f;

#pragma unroll 1
    for (int jt = 0; jt < 32; jt++) {
        CPWAIT(1); __syncthreads();
        uint32_t gb = Au + GB + (uint32_t)(jt&1)*16384;

        float acc[16][4];
#pragma unroll
        for (int nb = 0; nb < 16; nb++) { acc[nb][0]=0.f; acc[nb][1]=0.f; acc[nb][2]=0.f; acc[nb][3]=0.f; }

#pragma unroll
        for (int kk = 0; kk < 4; kk++) {
#pragma unroll
            for (int p = 0; p < 8; p++) {
                uint32_t off = swz((uint32_t)((p*16 + ((lane>>4)&1)*8 + (lane&7))*128
                                              + kk*32 + ((lane>>3)&1)*16));
                uint32_t bh[4];
                ldsm4(bh, gb+off);
                mma_f16(acc[2*p],   af[kk], &bh[0]);
                mma_f16(acc[2*p+1], af[kk], &bh[2]);
            }
        }
#pragma unroll
        for (int nb = 0; nb < 16; nb++) {
            z0 += ex2(acc[nb][0]) + ex2(acc[nb][1]);
            z1 += ex2(acc[nb][2]) + ex2(acc[nb][3]);
        }

        __syncthreads();
        if (jt+2 < 32) {
            const char* gq = (const char*)(g_gq + ((size_t)b*NPIX + (jt+2)*128)*CH);
            uint32_t base = Au + GB + (uint32_t)(jt&1)*16384;
            for (int q = t; q < 1024; q += 256) CP16(base+swz(q*16), gq + q*16);
        }
        CPCOMMIT();
    }

    // quad reduce (row i spread over lane&3)
    z0 += __shfl_xor_sync(0xFFFFFFFFu, z0, 1);
    z0 += __shfl_xor_sync(0xFFFFFFFFu, z0, 2);
    z1 += __shfl_xor_sync(0xFFFFFFFFu, z1, 1);
    z1 += __shfl_xor_sync(0xFFFFFFFFu, z1, 2);
    if ((lane&3) == 0) {
        int r = b*NPIX + i0 + wid*16 + (lane>>2);
        g_z[r]   = 1.0f/z0;
        g_z[r+8] = 1.0f/z1;
    }
}

// ---------------- Pass 2: out'[j,c] ------------------------------------------
// grid (32, 8), 256 threads. smem: G 16K + 2 x (f 8K + h 8K + rz 256B).
#define BUFST 16640u
#define B0    16384u
#define OF_FQ 0u
#define OF_HH 8192u
#define OF_RZ 16384u
__global__ __launch_bounds__(256,2) void pass2_hmma(
    const float* __restrict__ x, const float* __restrict__ gamma,
    float* __restrict__ out)
{
    extern __shared__ uint8_t dyn2[];
    uint8_t* A = (uint8_t*)(((uintptr_t)dyn2 + 1023) & ~(uintptr_t)1023);
    const uint32_t Au = smem_u32(A);

    const int t = threadIdx.x, lane = t&31, wid = t>>5;
    const int b = blockIdx.y, j0 = blockIdx.x*128;

    {
        const char* gq = (const char*)(g_gq + ((size_t)b*NPIX+j0)*CH);
        for (int q = t; q < 1024; q += 256) CP16(Au+swz(q*16), gq + q*16);
        CPCOMMIT();
    }
#pragma unroll 1
    for (int pre = 0; pre < 2; pre++) {
        const int i0 = pre*64;
        uint32_t base = Au + B0 + pre*BUFST;
        const char* fq = (const char*)(g_fq + ((size_t)b*NPIX+i0)*CH);
        for (int q = t; q < 512; q += 256) CP16(base+OF_FQ+swz(q*16), fq + q*16);
        const char* hq = (const char*)(g_hq + (size_t)b*CH*NPIX + i0);
        for (int q = t; q < 512; q += 256)
            CP16(base+OF_HH+swz(q*16), hq + (uint32_t)(q>>3)*NPIX*2 + (uint32_t)(q&7)*16);
        if (t < 16) CP16(base+OF_RZ + t*16, (const char*)(g_z + b*NPIX + i0) + t*16);
        CPCOMMIT();
    }
    CPWAIT(2); __syncthreads();

    uint32_t ag[4][4];
#pragma unroll
    for (int kk = 0; kk < 4; kk++) {
        uint32_t off = swz((uint32_t)((wid*16 + (lane&15))*128 + kk*32 + ((lane>>4)&1)*16));
        ldsm4(ag[kk], Au+off);
    }

    float oacc[8][4];
#pragma unroll
    for (int nb = 0; nb < 8; nb++) { oacc[nb][0]=0.f; oacc[nb][1]=0.f; oacc[nb][2]=0.f; oacc[nb][3]=0.f; }

#pragma unroll 1
    for (int it = 0; it < 64; it++) {
        CPWAIT(1); __syncthreads();
        uint32_t bb = Au + B0 + (uint32_t)(it&1)*BUFST;
        const float* rz = (const float*)(A + B0 + (it&1)*BUFST + OF_RZ);

        // GEMM1': S'[16 j/warp, 64 i] = g . f^T (single-term)
        float sacc[8][4];
#pragma unroll
        for (int nb = 0; nb < 8; nb++) { sacc[nb][0]=0.f; sacc[nb][1]=0.f; sacc[nb][2]=0.f; sacc[nb][3]=0.f; }
#pragma unroll
        for (int kk = 0; kk < 4; kk++) {
#pragma unroll
            for (int p = 0; p < 4; p++) {
                uint32_t off = swz((uint32_t)((p*16 + ((lane>>4)&1)*8 + (lane&7))*128
                                              + kk*32 + ((lane>>3)&1)*16));
                uint32_t bh[4];
                ldsm4(bh, bb+OF_FQ+off);
                mma_f16(sacc[2*p],   ag[kk], &bh[0]);
                mma_f16(sacc[2*p+1], ag[kk], &bh[2]);
            }
        }

        // P' = exp2(s') * (1/Z), fp16 single, then GEMM2
#pragma unroll
        for (int kk2 = 0; kk2 < 4; kk2++) {
            uint32_t aH[4];
#pragma unroll
            for (int u = 0; u < 2; u++) {
                int nb = 2*kk2 + u;
                int ic = nb*8 + (lane&3)*2;
                float r0v = rz[ic], r1v = rz[ic+1];
                aH[0+u*2] = pack2h(__float2half_rn(ex2(sacc[nb][0])*r0v),
                                   __float2half_rn(ex2(sacc[nb][1])*r1v));
                aH[1+u*2] = pack2h(__float2half_rn(ex2(sacc[nb][2])*r0v),
                                   __float2half_rn(ex2(sacc[nb][3])*r1v));
            }
#pragma unroll
            for (int p = 0; p < 4; p++) {
                uint32_t off = swz((uint32_t)((p*16 + ((lane>>4)&1)*8 + (lane&7))*128
                                              + kk2*32 + ((lane>>3)&1)*16));
                uint32_t bh[4];
                ldsm4(bh, bb+OF_HH+off);
                mma_f16(oacc[2*p],   aH, &bh[0]);
                mma_f16(oacc[2*p+1], aH, &bh[2]);
            }
        }

        __syncthreads();
        if (it+2 < 64) {
            const int i0 = (it+2)*64;
            uint32_t base = Au + B0 + (uint32_t)(it&1)*BUFST;
            const char* fq = (const char*)(g_fq + ((size_t)b*NPIX+i0)*CH);
            for (int q = t; q < 512; q += 256) CP16(base+OF_FQ+swz(q*16), fq + q*16);
            const char* hq = (const char*)(g_hq + (size_t)b*CH*NPIX + i0);
            for (int q = t; q < 512; q += 256)
                CP16(base+OF_HH+swz(q*16), hq + (uint32_t)(q>>3)*NPIX*2 + (uint32_t)(q&7)*16);
            if (t < 16) CP16(base+OF_RZ + t*16, (const char*)(g_z + b*NPIX + i0) + t*16);
        }
        CPCOMMIT();
    }

    // Epilogue: stage [64 c][128 j] fp32 in smem, coalesced gamma*o + x
    CPWAIT(0); __syncthreads();
    float* outs = (float*)(A + B0);
    const int jl = wid*16 + (lane>>2);
#pragma unroll
    for (int nb = 0; nb < 8; nb++) {
        int c0 = nb*8 + (lane&3)*2;
        outs[c0*128 + jl]         = oacc[nb][0];
        outs[(c0+1)*128 + jl]     = oacc[nb][1];
        outs[c0*128 + jl + 8]     = oacc[nb][2];
        outs[(c0+1)*128 + jl + 8] = oacc[nb][3];
    }
    __syncthreads();
    const float gam = *gamma;
    {
        const int row = t>>2, seg = t&3;
        const float* xr   = x   + ((size_t)b*CH + row)*NPIX + j0 + seg*32;
        float*       orow = out + ((size_t)b*CH + row)*NPIX + j0 + seg*32;
        const float4* sr = (const float4*)(outs + row*128 + seg*32);
#pragma unroll
        for (int u = 0; u < 8; u++) {
            float4 v = sr[u];
            float4 xv = *(const float4*)(xr + u*4);
            float4 r;
            r.x = gam*v.x + xv.x; r.y = gam*v.y + xv.y;
            r.z = gam*v.z + xv.z; r.w = gam*v.w + xv.w;
            *(float4*)(orow + u*4) = r;
        }
    }
}

// -----------------------------------------------------------------------------
extern "C" void kernel_launch(void* const* d_in, const int* in_sizes, int n_in,
                              void* d_out, int out_size)
{
    const float* x     = (const float*)d_in[0];
    const float* Wf    = (const float*)d_in[1];
    const float* bf    = (const float*)d_in[2];
    const float* Wg    = (const float*)d_in[3];
    const float* bg    = (const float*)d_in[4];
    const float* Wh    = (const float*)d_in[5];
    const float* bh    = (const float*)d_in[6];
    const float* gamma = (const float*)d_in[7];
    float* out = (float*)d_out;
    (void)in_sizes; (void)n_in; (void)out_size;

    cudaFuncSetAttribute(pass1_hmma, cudaFuncAttributeMaxDynamicSharedMemorySize, 49152+1024);
    cudaFuncSetAttribute(pass2_hmma, cudaFuncAttributeMaxDynamicSharedMemorySize, 16384+2*16640+1024);

    fgh_proj<<<dim3(NPIX/128, BATCH, 3), 128>>>(x, Wf, bf, Wg, bg, Wh, bh);
    pass1_hmma<<<dim3(32, BATCH), 256, 49152+1024>>>();
    pass2_hmma<<<dim3(32, BATCH), 256, 16384+2*16640+1024>>>(x, gamma, out);
}

// round 7
// speedup vs baseline: 6.7154x; 1.1517x over previous
#include <cuda_runtime.h>
#include <cuda_fp16.h>
#include <cstdint>

#define BATCH 8
#define CH    64
#define NPIX  4096

// Scratch. f pre-scaled by log2(e); g_L stores log2(Z).
__device__ __align__(128) __half g_fq[BATCH*NPIX*CH]; // f*log2e [b][n][c]
__device__ __align__(128) __half g_gq[BATCH*NPIX*CH]; // g       [b][n][c]
__device__ __align__(128) __half g_hq[BATCH*CH*NPIX]; // h       [b][c][n]
__device__ float g_L[BATCH*NPIX];

__device__ __forceinline__ uint32_t smem_u32(const void* p){
    uint32_t a; asm("{ .reg .u64 t; cvta.to.shared.u64 t, %1; cvt.u32.u64 %0, t; }":"=r"(a):"l"(p)); return a;
}
__device__ __forceinline__ uint32_t swz(uint32_t o){ return o ^ ((o>>3)&0x70); }   // 128B rows
__device__ __forceinline__ uint32_t swzH(uint32_t o){ return o ^ ((o>>4)&0x70); }  // 256B rows
__device__ __forceinline__ float ex2(float x){
    float y; asm("ex2.approx.f32 %0, %1;":"=f"(y):"f"(x)); return y;
}
__device__ __forceinline__ float lg2(float x){
    float y; asm("lg2.approx.f32 %0, %1;":"=f"(y):"f"(x)); return y;
}
__device__ __forceinline__ uint32_t cvtpack(float lo, float hi){
    uint32_t r; asm("cvt.rn.f16x2.f32 %0, %1, %2;" : "=r"(r) : "f"(hi), "f"(lo)); return r;
}
__device__ __forceinline__ uint32_t sub2(uint32_t a, uint32_t b){
    uint32_t r; asm("sub.rn.f16x2 %0, %1, %2;" : "=r"(r) : "r"(a), "r"(b)); return r;
}
__device__ __forceinline__ uint32_t ex2h2(uint32_t a){
    uint32_t r; asm("ex2.approx.f16x2 %0, %1;" : "=r"(r) : "r"(a)); return r;
}
#define CP16(dst, src) asm volatile("cp.async.cg.shared.global [%0], [%1], 16;"::"r"(dst),"l"(src):"memory")
#define CPCOMMIT()     asm volatile("cp.async.commit_group;":::"memory")
#define CPWAIT(n)      asm volatile("cp.async.wait_group %0;"::"n"(n):"memory")

__device__ __forceinline__ void ldsm4(uint32_t r[4], uint32_t addr){
    asm volatile("ldmatrix.sync.aligned.m8n8.x4.shared.b16 {%0,%1,%2,%3},[%4];"
        : "=r"(r[0]),"=r"(r[1]),"=r"(r[2]),"=r"(r[3]) : "r"(addr));
}
__device__ __forceinline__ void ldsm4t(uint32_t r[4], uint32_t addr){
    asm volatile("ldmatrix.sync.aligned.m8n8.x4.trans.shared.b16 {%0,%1,%2,%3},[%4];"
        : "=r"(r[0]),"=r"(r[1]),"=r"(r[2]),"=r"(r[3]) : "r"(addr));
}
__device__ __forceinline__ void mma_f16(float d[4], const uint32_t a[4], const uint32_t b[2]){
    asm volatile("mma.sync.aligned.m16n8k16.row.col.f32.f16.f16.f32 "
        "{%0,%1,%2,%3},{%4,%5,%6,%7},{%8,%9},{%0,%1,%2,%3};"
        : "+f"(d[0]),"+f"(d[1]),"+f"(d[2]),"+f"(d[3])
        : "r"(a[0]),"r"(a[1]),"r"(a[2]),"r"(a[3]),"r"(b[0]),"r"(b[1]));
}
__device__ __forceinline__ void mma_h16(uint32_t d[2], const uint32_t a[4], const uint32_t b[2]){
    asm volatile("mma.sync.aligned.m16n8k16.row.col.f16.f16.f16.f16 "
        "{%0,%1},{%2,%3,%4,%5},{%6,%7},{%0,%1};"
        : "+r"(d[0]),"+r"(d[1])
        : "r"(a[0]),"r"(a[1]),"r"(a[2]),"r"(a[3]),"r"(b[0]),"r"(b[1]));
}

// ---------------- Stage A: projections via HMMA ------------------------------
// grid (32, 8), 256 threads. smem: W 3x8K | bias 1K | X 16K | stage 16K = 58368
__global__ __launch_bounds__(256,2) void fgh_hmma(
    const float* __restrict__ x,
    const float* __restrict__ Wf, const float* __restrict__ bf,
    const float* __restrict__ Wg, const float* __restrict__ bg,
    const float* __restrict__ Wh, const float* __restrict__ bh)
{
    extern __shared__ uint8_t dyn0[];
    uint8_t* A = (uint8_t*)(((uintptr_t)dyn0 + 1023) & ~(uintptr_t)1023);
    const uint32_t Au = smem_u32(A);
    const uint32_t BIAS=24576, SX=25600, STG=41984;

    const int t = threadIdx.x, lane = t&31, wid = t>>5;
    const int b = blockIdx.y, n0 = blockIdx.x*128;

    // W -> fp16 smem [o][k], swz 128B rows. Wf scaled by log2e.
    for (int q = t; q < 3*4096; q += 256) {
        int mtx = q >> 12, idx = q & 4095;
        const float* Wsrc = (mtx==0)?Wf:((mtx==1)?Wg:Wh);
        float v = Wsrc[idx] * ((mtx==0) ? 1.44269504f : 1.0f);
        int o = idx >> 6, k = idx & 63;
        *(__half*)(A + mtx*8192u + swz(o*128 + k*2)) = __float2half_rn(v);
    }
    if (t < 192) {
        const float* bsrc = (t<64)?bf:((t<128)?bg:bh);
        ((float*)(A+BIAS))[t] = bsrc[t&63] * ((t<64) ? 1.44269504f : 1.0f);
    }
    // x tile -> fp16 smem [k=c][n], swzH 256B rows
    {
        int c = t>>2, nb0 = (t&3)*32;
        const float* xr = x + ((size_t)b*CH + c)*NPIX + n0 + nb0;
        for (int u = 0; u < 16; u++) {
            float2 v = *(const float2*)(xr + 2*u);
            *(uint32_t*)(A + SX + swzH((uint32_t)(c*256 + (nb0+2*u)*2))) = cvtpack(v.x, v.y);
        }
    }
    __syncthreads();

    // A-frags = x^T via ldsm.trans
    uint32_t ax[4][4];
    const int m0 = wid*16;
#pragma unroll
    for (int kk = 0; kk < 4; kk++) {
        int row = kk*16 + (lane&7) + ((lane>>4)<<3);
        int col = m0 + ((lane>>3)&1)*8;
        ldsm4t(ax[kk], Au + SX + swzH((uint32_t)(row*256 + col*2)));
    }
    const float* bias = (const float*)(A+BIAS);

#pragma unroll 1
    for (int mtx = 0; mtx < 3; mtx++) {
        float acc[8][4];
#pragma unroll
        for (int ob = 0; ob < 8; ob++) {
            float b0 = bias[mtx*64 + ob*8 + (lane&3)*2];
            float b1 = bias[mtx*64 + ob*8 + (lane&3)*2 + 1];
            acc[ob][0]=b0; acc[ob][1]=b1; acc[ob][2]=b0; acc[ob][3]=b1;
        }
#pragma unroll
        for (int kk = 0; kk < 4; kk++) {
#pragma unroll
            for (int op = 0; op < 4; op++) {
                uint32_t off = swz((uint32_t)((op*16 + ((lane>>4)&1)*8 + (lane&7))*128
                                              + kk*32 + ((lane>>3)&1)*16));
                uint32_t bw[4];
                ldsm4(bw, Au + mtx*8192u + off);
                mma_f16(acc[2*op],   ax[kk], &bw[0]);
                mma_f16(acc[2*op+1], ax[kk], &bw[2]);
            }
        }
        // stage [n][o] fp16 (swz 128B rows)
        __syncthreads();
#pragma unroll
        for (int ob = 0; ob < 8; ob++) {
            int o = ob*8 + (lane&3)*2, r = lane>>2;
            *(uint32_t*)(A + STG + swz((uint32_t)((m0+r)*128   + o*2))) = cvtpack(acc[ob][0], acc[ob][1]);
            *(uint32_t*)(A + STG + swz((uint32_t)((m0+r+8)*128 + o*2))) = cvtpack(acc[ob][2], acc[ob][3]);
        }
        __syncthreads();
        if (mtx < 2) {
            __half* dst = ((mtx==0)?g_fq:g_gq) + ((size_t)b*NPIX + n0)*CH;
            int n = t>>1, half = t&1;
#pragma unroll
            for (int q16 = 0; q16 < 4; q16++) {
                int4 v = *(int4*)(A + STG + swz((uint32_t)(n*128 + half*64 + q16*16)));
                *(int4*)((char*)(dst + (size_t)n*CH + half*32) + q16*16) = v;
            }
        } else {
            int c = t>>2, sg = t&3;
            __half* dst = g_hq + ((size_t)b*CH + c)*NPIX + n0 + sg*32;
#pragma unroll
            for (int u = 0; u < 16; u++) {
                int n = sg*32 + 2*u;
                uint32_t e0 = *(uint16_t*)(A + STG + swz((uint32_t)(n*128 + c*2)));
                uint32_t e1 = *(uint16_t*)(A + STG + swz((uint32_t)((n+1)*128 + c*2)));
                *(uint32_t*)(dst + 2*u) = e0 | (e1<<16);
            }
        }
    }
}

// ---------------- Pass 1: L[i] = log2(Z_i) -----------------------------------
// grid (32, 8), 256 threads. smem: F 16K | G dbl 2x16K = 48K.
__global__ __launch_bounds__(256,2) void pass1_hmma()
{
    extern __shared__ uint8_t dyn1[];
    uint8_t* A = (uint8_t*)(((uintptr_t)dyn1 + 1023) & ~(uintptr_t)1023);
    const uint32_t Au = smem_u32(A);
    const uint32_t FQ=0, GB=16384;

    const int t = threadIdx.x, lane = t&31, wid = t>>5;
    const int b = blockIdx.y, i0 = blockIdx.x*128;

    {
        const char* fq = (const char*)(g_fq + ((size_t)b*NPIX+i0)*CH);
        for (int q = t; q < 1024; q += 256) CP16(Au+FQ+swz(q*16), fq + q*16);
        CPCOMMIT();
    }
#pragma unroll 1
    for (int pre = 0; pre < 2; pre++) {
        const char* gq = (const char*)(g_gq + ((size_t)b*NPIX + pre*128)*CH);
        uint32_t base = Au + GB + pre*16384;
        for (int q = t; q < 1024; q += 256) CP16(base+swz(q*16), gq + q*16);
        CPCOMMIT();
    }
    CPWAIT(2); __syncthreads();

    uint32_t af[4][4];
#pragma unroll
    for (int kk = 0; kk < 4; kk++) {
        uint32_t off = swz((uint32_t)((wid*16 + (lane&15))*128 + kk*32 + ((lane>>4)&1)*16));
        ldsm4(af[kk], Au+FQ+off);
    }

    float z0 = 0.f, z1 = 0.f;

#pragma unroll 1
    for (int jt = 0; jt < 32; jt++) {
        CPWAIT(1); __syncthreads();
        uint32_t gb = Au + GB + (uint32_t)(jt&1)*16384;

        float acc[16][4];
#pragma unroll
        for (int nb = 0; nb < 16; nb++) { acc[nb][0]=0.f; acc[nb][1]=0.f; acc[nb][2]=0.f; acc[nb][3]=0.f; }

#pragma unroll
        for (int kk = 0; kk < 4; kk++) {
#pragma unroll
            for (int p = 0; p < 8; p++) {
                uint32_t off = swz((uint32_t)((p*16 + ((lane>>4)&1)*8 + (lane&7))*128
                                              + kk*32 + ((lane>>3)&1)*16));
                uint32_t bh[4];
                ldsm4(bh, gb+off);
                mma_f16(acc[2*p],   af[kk], &bh[0]);
                mma_f16(acc[2*p+1], af[kk], &bh[2]);
            }
        }
#pragma unroll
        for (int nb = 0; nb < 16; nb++) {
            z0 += ex2(acc[nb][0]) + ex2(acc[nb][1]);
            z1 += ex2(acc[nb][2]) + ex2(acc[nb][3]);
        }

        __syncthreads();
        if (jt+2 < 32) {
            const char* gq = (const char*)(g_gq + ((size_t)b*NPIX + (jt+2)*128)*CH);
            uint32_t base = Au + GB + (uint32_t)(jt&1)*16384;
            for (int q = t; q < 1024; q += 256) CP16(base+swz(q*16), gq + q*16);
        }
        CPCOMMIT();
    }

    z0 += __shfl_xor_sync(0xFFFFFFFFu, z0, 1);
    z0 += __shfl_xor_sync(0xFFFFFFFFu, z0, 2);
    z1 += __shfl_xor_sync(0xFFFFFFFFu, z1, 1);
    z1 += __shfl_xor_sync(0xFFFFFFFFu, z1, 2);
    if ((lane&3) == 0) {
        int r = b*NPIX + i0 + wid*16 + (lane>>2);
        g_L[r]   = lg2(z0);
        g_L[r+8] = lg2(z1);
    }
}

// ---------------- Pass 2: out'[j,c], log2-domain fp16 ------------------------
// grid (32, 8), 256 threads. smem: G 16K + 2 x (f 8K + h 8K + L 256B).
#define BUFST 16640u
#define B0    16384u
#define OF_FQ 0u
#define OF_HH 8192u
#define OF_L  16384u
__global__ __launch_bounds__(256,2) void pass2_hmma(
    const float* __restrict__ x, const float* __restrict__ gamma,
    float* __restrict__ out)
{
    extern __shared__ uint8_t dyn2[];
    uint8_t* A = (uint8_t*)(((uintptr_t)dyn2 + 1023) & ~(uintptr_t)1023);
    const uint32_t Au = smem_u32(A);

    const int t = threadIdx.x, lane = t&31, wid = t>>5;
    const int b = blockIdx.y, j0 = blockIdx.x*128;

    {
        const char* gq = (const char*)(g_gq + ((size_t)b*NPIX+j0)*CH);
        for (int q = t; q < 1024; q += 256) CP16(Au+swz(q*16), gq + q*16);
        CPCOMMIT();
    }
#pragma unroll 1
    for (int pre = 0; pre < 2; pre++) {
        const int i0 = pre*64;
        uint32_t base = Au + B0 + pre*BUFST;
        const char* fq = (const char*)(g_fq + ((size_t)b*NPIX+i0)*CH);
        for (int q = t; q < 512; q += 256) CP16(base+OF_FQ+swz(q*16), fq + q*16);
        const char* hq = (const char*)(g_hq + (size_t)b*CH*NPIX + i0);
        for (int q = t; q < 512; q += 256)
            CP16(base+OF_HH+swz(q*16), hq + (uint32_t)(q>>3)*NPIX*2 + (uint32_t)(q&7)*16);
        if (t < 16) CP16(base+OF_L + t*16, (const char*)(g_L + b*NPIX + i0) + t*16);
        CPCOMMIT();
    }
    CPWAIT(2); __syncthreads();

    uint32_t ag[4][4];
#pragma unroll
    for (int kk = 0; kk < 4; kk++) {
        uint32_t off = swz((uint32_t)((wid*16 + (lane&15))*128 + kk*32 + ((lane>>4)&1)*16));
        ldsm4(ag[kk], Au+off);
    }

    float oacc[8][4];
#pragma unroll
    for (int nb = 0; nb < 8; nb++) { oacc[nb][0]=0.f; oacc[nb][1]=0.f; oacc[nb][2]=0.f; oacc[nb][3]=0.f; }

#pragma unroll 1
    for (int it = 0; it < 64; it++) {
        CPWAIT(1); __syncthreads();
        uint32_t bb = Au + B0 + (uint32_t)(it&1)*BUFST;
        const float* Lf = (const float*)(A + B0 + (it&1)*BUFST + OF_L);

        // pack L pairs per thread (cols 2q,2q+1 of each i-block)
        uint32_t L2[8];
#pragma unroll
        for (int nb = 0; nb < 8; nb++) {
            int ic = nb*8 + (lane&3)*2;
            L2[nb] = cvtpack(Lf[ic], Lf[ic+1]);
        }

        // GEMM1': S'[16 j/warp, 64 i] = g . f^T, fp16 accumulators
        uint32_t sacc[8][2];
#pragma unroll
        for (int nb = 0; nb < 8; nb++) { sacc[nb][0]=0u; sacc[nb][1]=0u; }
#pragma unroll
        for (int kk = 0; kk < 4; kk++) {
#pragma unroll
            for (int p = 0; p < 4; p++) {
                uint32_t off = swz((uint32_t)((p*16 + ((lane>>4)&1)*8 + (lane&7))*128
                                              + kk*32 + ((lane>>3)&1)*16));
                uint32_t bh[4];
                ldsm4(bh, bb+OF_FQ+off);
                mma_h16(sacc[2*p],   ag[kk], &bh[0]);
                mma_h16(sacc[2*p+1], ag[kk], &bh[2]);
            }
        }

        // P' = exp2(s - L) in f16x2 -> direct A-frags; GEMM2 fp32 accum
#pragma unroll
        for (int kk2 = 0; kk2 < 4; kk2++) {
            int nb0 = 2*kk2, nb1 = nb0+1;
            uint32_t aH[4];
            aH[0] = ex2h2(sub2(sacc[nb0][0], L2[nb0]));
            aH[1] = ex2h2(sub2(sacc[nb0][1], L2[nb0]));
            aH[2] = ex2h2(sub2(sacc[nb1][0], L2[nb1]));
            aH[3] = ex2h2(sub2(sacc[nb1][1], L2[nb1]));
#pragma unroll
            for (int p = 0; p < 4; p++) {
                uint32_t off = swz((uint32_t)((p*16 + ((lane>>4)&1)*8 + (lane&7))*128
                                              + kk2*32 + ((lane>>3)&1)*16));
                uint32_t bh[4];
                ldsm4(bh, bb+OF_HH+off);
                mma_f16(oacc[2*p],   aH, &bh[0]);
                mma_f16(oacc[2*p+1], aH, &bh[2]);
            }
        }

        __syncthreads();
        if (it+2 < 64) {
            const int i0 = (it+2)*64;
            uint32_t base = Au + B0 + (uint32_t)(it&1)*BUFST;
            const char* fq = (const char*)(g_fq + ((size_t)b*NPIX+i0)*CH);
            for (int q = t; q < 512; q += 256) CP16(base+OF_FQ+swz(q*16), fq + q*16);
            const char* hq = (const char*)(g_hq + (size_t)b*CH*NPIX + i0);
            for (int q = t; q < 512; q += 256)
                CP16(base+OF_HH+swz(q*16), hq + (uint32_t)(q>>3)*NPIX*2 + (uint32_t)(q&7)*16);
            if (t < 16) CP16(base+OF_L + t*16, (const char*)(g_L + b*NPIX + i0) + t*16);
        }
        CPCOMMIT();
    }

    // Epilogue: stage [64 c][128 j] fp32 in smem, coalesced gamma*o + x
    CPWAIT(0); __syncthreads();
    float* outs = (float*)(A + B0);
    const int jl = wid*16 + (lane>>2);
#pragma unroll
    for (int nb = 0; nb < 8; nb++) {
        int c0 = nb*8 + (lane&3)*2;
        outs[c0*128 + jl]         = oacc[nb][0];
        outs[(c0+1)*128 + jl]     = oacc[nb][1];
        outs[c0*128 + jl + 8]     = oacc[nb][2];
        outs[(c0+1)*128 + jl + 8] = oacc[nb][3];
    }
    __syncthreads();
    const float gam = *gamma;
    {
        const int row = t>>2, seg = t&3;
        const float* xr   = x   + ((size_t)b*CH + row)*NPIX + j0 + seg*32;
        float*       orow = out + ((size_t)b*CH + row)*NPIX + j0 + seg*32;
        const float4* sr = (const float4*)(outs + row*128 + seg*32);
#pragma unroll
        for (int u = 0; u < 8; u++) {
            float4 v = sr[u];
            float4 xv = *(const float4*)(xr + u*4);
            float4 r;
            r.x = gam*v.x + xv.x; r.y = gam*v.y + xv.y;
            r.z = gam*v.z + xv.z; r.w = gam*v.w + xv.w;
            *(float4*)(orow + u*4) = r;
        }
    }
}

// -----------------------------------------------------------------------------
extern "C" void kernel_launch(void* const* d_in, const int* in_sizes, int n_in,
                              void* d_out, int out_size)
{
    const float* x     = (const float*)d_in[0];
    const float* Wf    = (const float*)d_in[1];
    const float* bf    = (const float*)d_in[2];
    const float* Wg    = (const float*)d_in[3];
    const float* bg    = (const float*)d_in[4];
    const float* Wh    = (const float*)d_in[5];
    const float* bh    = (const float*)d_in[6];
    const float* gamma = (const float*)d_in[7];
    float* out = (float*)d_out;
    (void)in_sizes; (void)n_in; (void)out_size;

    cudaFuncSetAttribute(fgh_hmma,   cudaFuncAttributeMaxDynamicSharedMemorySize, 58368+1024);
    cudaFuncSetAttribute(pass1_hmma, cudaFuncAttributeMaxDynamicSharedMemorySize, 49152+1024);
    cudaFuncSetAttribute(pass2_hmma, cudaFuncAttributeMaxDynamicSharedMemorySize, 16384+2*16640+1024);

    fgh_hmma<<<dim3(32, BATCH), 256, 58368+1024>>>(x, Wf, bf, Wg, bg, Wh, bh);
    pass1_hmma<<<dim3(32, BATCH), 256, 49152+1024>>>();
    pass2_hmma<<<dim3(32, BATCH), 256, 16384+2*16640+1024>>>(x, gamma, out);
}